// round 5
// baseline (speedup 1.0000x reference)
#include <cuda_runtime.h>
#include <math.h>
#include <stdint.h>

#define TOK   4096
#define DIM   1024
#define NEXP  8
#define EHID  2816
#define SHID  1536
#define LDI   80            // smem row stride bytes (64 data + 16 pad)

// ---------------- scratch (device globals) ----------------------------------
__device__ int8_t g_xqh[(size_t)TOK*DIM];
__device__ int8_t g_xql[(size_t)TOK*DIM];
__device__ float  g_sx [TOK];
__device__ int8_t g_w1qh[(size_t)NEXP*EHID*DIM], g_w1ql[(size_t)NEXP*EHID*DIM];
__device__ int8_t g_w3qh[(size_t)NEXP*EHID*DIM], g_w3ql[(size_t)NEXP*EHID*DIM];
__device__ int8_t g_w2qh[(size_t)NEXP*DIM*EHID], g_w2ql[(size_t)NEXP*DIM*EHID];
__device__ float  g_sw1[NEXP*EHID], g_sw3[NEXP*EHID], g_sw2[NEXP*DIM];
__device__ int8_t g_s1qh[(size_t)SHID*DIM], g_s1ql[(size_t)SHID*DIM];
__device__ int8_t g_s3qh[(size_t)SHID*DIM], g_s3ql[(size_t)SHID*DIM];
__device__ int8_t g_s2qh[(size_t)DIM*SHID], g_s2ql[(size_t)DIM*SHID];
__device__ float  g_ss1[SHID], g_ss3[SHID], g_ss2[DIM];
__device__ float  g_hf [(size_t)NEXP*TOK*EHID];     // routed hidden fp32
__device__ int8_t g_hqh[(size_t)NEXP*TOK*EHID], g_hql[(size_t)NEXP*TOK*EHID];
__device__ float  g_sh [NEXP*TOK];
__device__ float  g_hsf[(size_t)TOK*SHID];          // shared hidden fp32
__device__ int8_t g_hsqh[(size_t)TOK*SHID], g_hsql[(size_t)TOK*SHID];
__device__ float  g_shs[TOK];
__device__ float  g_yp [(size_t)NEXP*TOK*DIM];
__device__ int    g_cnt[NEXP];
__device__ int    g_idx[NEXP*TOK];
__device__ float  g_wgt[NEXP*TOK];
__device__ int    g_slot[TOK*2];

// ---------------- helpers ----------------------------------------------------
__device__ __forceinline__ uint32_t smem_u32(const void* p) {
    uint32_t a;
    asm("{ .reg .u64 t; cvta.to.shared.u64 t, %1; cvt.u32.u64 %0, t; }"
        : "=r"(a) : "l"(p));
    return a;
}
__device__ __forceinline__ void cp16(uint32_t saddr, const void* g, bool valid) {
    int sz = valid ? 16 : 0;
    asm volatile("cp.async.cg.shared.global [%0], [%1], 16, %2;"
                 :: "r"(saddr), "l"(g), "r"(sz));
}
#define CP_COMMIT() asm volatile("cp.async.commit_group;")
#define CP_WAIT1()  asm volatile("cp.async.wait_group 1;")
#define CP_WAIT0()  asm volatile("cp.async.wait_group 0;")

#define LDSM4(r, addr) \
    asm volatile("ldmatrix.sync.aligned.m8n8.x4.shared.b16 {%0,%1,%2,%3}, [%4];" \
        : "=r"((r)[0]), "=r"((r)[1]), "=r"((r)[2]), "=r"((r)[3]) : "r"(addr))

__device__ __forceinline__ void mma_s8(int d[4], const uint32_t a[4],
                                       uint32_t b0, uint32_t b1) {
    asm volatile(
        "mma.sync.aligned.m16n8k32.row.col.s32.s8.s8.s32 "
        "{%0,%1,%2,%3},{%4,%5,%6,%7},{%8,%9},{%0,%1,%2,%3};"
        : "+r"(d[0]), "+r"(d[1]), "+r"(d[2]), "+r"(d[3])
        : "r"(a[0]), "r"(a[1]), "r"(a[2]), "r"(a[3]), "r"(b0), "r"(b1));
}

// ---------------- small kernels ------------------------------------------------
__global__ void zero_counts_kernel() {
    if (threadIdx.x < NEXP) g_cnt[threadIdx.x] = 0;
}

__global__ void gate_kernel(const float* __restrict__ x, const float* __restrict__ gw) {
    int tok  = (blockIdx.x * blockDim.x + threadIdx.x) >> 5;
    int lane = threadIdx.x & 31;
    if (tok >= TOK) return;
    const float* xr = x + (size_t)tok * DIM;
    float acc[NEXP];
#pragma unroll
    for (int e = 0; e < NEXP; e++) acc[e] = 0.f;
    for (int d = lane; d < DIM; d += 32) {
        float xv = xr[d];
#pragma unroll
        for (int e = 0; e < NEXP; e++) acc[e] = fmaf(xv, gw[e * DIM + d], acc[e]);
    }
#pragma unroll
    for (int e = 0; e < NEXP; e++)
#pragma unroll
        for (int off = 16; off > 0; off >>= 1)
            acc[e] += __shfl_xor_sync(0xffffffffu, acc[e], off);
    if (lane == 0) {
        float mx = acc[0];
#pragma unroll
        for (int e = 1; e < NEXP; e++) mx = fmaxf(mx, acc[e]);
        float p[NEXP], s = 0.f;
#pragma unroll
        for (int e = 0; e < NEXP; e++) { p[e] = expf(acc[e] - mx); s += p[e]; }
        float inv = 1.f / s;
#pragma unroll
        for (int e = 0; e < NEXP; e++) p[e] *= inv;
        int i1 = 0;
#pragma unroll
        for (int e = 1; e < NEXP; e++) if (p[e] > p[i1]) i1 = e;
        int i2 = (i1 == 0) ? 1 : 0;
#pragma unroll
        for (int e = 0; e < NEXP; e++) if (e != i1 && p[e] > p[i2]) i2 = e;
        int pos1 = atomicAdd(&g_cnt[i1], 1);
        g_idx[i1 * TOK + pos1] = tok;  g_wgt[i1 * TOK + pos1] = p[i1];
        g_slot[2 * tok] = i1 * TOK + pos1;
        int pos2 = atomicAdd(&g_cnt[i2], 1);
        g_idx[i2 * TOK + pos2] = tok;  g_wgt[i2 * TOK + pos2] = p[i2];
        g_slot[2 * tok + 1] = i2 * TOK + pos2;
    }
}

// per-row two-level int8 quantization. One block (256 thr) per row.
__global__ void quant_rows_kernel(const float* __restrict__ in,
                                  int8_t* __restrict__ qh, int8_t* __restrict__ ql,
                                  float* __restrict__ scale, int K, int checkCnt) {
    int row = blockIdx.x;
    if (checkCnt) {
        int e = row >> 12, pos = row & (TOK - 1);
        if (pos >= g_cnt[e]) return;
    }
    const float4* src = reinterpret_cast<const float4*>(in + (size_t)row * K);
    int K4 = K >> 2;
    float mx = 0.f;
    for (int j = threadIdx.x; j < K4; j += 256) {
        float4 v = src[j];
        mx = fmaxf(mx, fmaxf(fmaxf(fabsf(v.x), fabsf(v.y)),
                             fmaxf(fabsf(v.z), fabsf(v.w))));
    }
#pragma unroll
    for (int off = 16; off > 0; off >>= 1)
        mx = fmaxf(mx, __shfl_xor_sync(0xffffffffu, mx, off));
    __shared__ float red[8];
    int wid = threadIdx.x >> 5;
    if ((threadIdx.x & 31) == 0) red[wid] = mx;
    __syncthreads();
    mx = red[0];
#pragma unroll
    for (int w = 1; w < 8; w++) mx = fmaxf(mx, red[w]);

    float s   = (mx > 0.f) ? mx * (1.f / 127.f) : 1.f;
    float inv = (mx > 0.f) ? 127.f / mx : 0.f;
    if (threadIdx.x == 0) scale[row] = s;
    char4* dh = reinterpret_cast<char4*>(qh + (size_t)row * K);
    char4* dl = reinterpret_cast<char4*>(ql + (size_t)row * K);
    for (int j = threadIdx.x; j < K4; j += 256) {
        float4 v = src[j];
        float q0 = rintf(v.x * inv), q1 = rintf(v.y * inv);
        float q2 = rintf(v.z * inv), q3 = rintf(v.w * inv);
        float l0 = fminf(127.f, fmaxf(-127.f, rintf((v.x - q0 * s) * inv * 256.f)));
        float l1 = fminf(127.f, fmaxf(-127.f, rintf((v.y - q1 * s) * inv * 256.f)));
        float l2 = fminf(127.f, fmaxf(-127.f, rintf((v.z - q2 * s) * inv * 256.f)));
        float l3 = fminf(127.f, fmaxf(-127.f, rintf((v.w - q3 * s) * inv * 256.f)));
        dh[j] = make_char4((int8_t)q0, (int8_t)q1, (int8_t)q2, (int8_t)q3);
        dl[j] = make_char4((int8_t)l0, (int8_t)l1, (int8_t)l2, (int8_t)l3);
    }
}

// column abs-max of in [z][K][N] -> s[z][n] = max/127
__global__ void colmax_kernel(const float* __restrict__ in, float* __restrict__ sc,
                              int K, int N) {
    size_t z = blockIdx.y;
    in += z * (size_t)K * N;
    sc += z * (size_t)N;
    int n = blockIdx.x * 256 + threadIdx.x;
    if (n >= N) return;
    float m = 0.f;
    for (int k = 0; k < K; k++) m = fmaxf(m, fabsf(in[(size_t)k * N + n]));
    sc[n] = (m > 0.f) ? m * (1.f / 127.f) : 1.f;
}

// transpose + quantize: in [z][K][N] fp32 -> qh/ql [z][N][K] int8 (scale per n)
__global__ void cvtTq_kernel(const float* __restrict__ in, const float* __restrict__ sc,
                             int8_t* __restrict__ qh, int8_t* __restrict__ ql,
                             int K, int N) {
    __shared__ float tile[32][33];
    size_t z = blockIdx.z;
    in += z * (size_t)K * N;
    qh += z * (size_t)N * K;
    ql += z * (size_t)N * K;
    sc += z * (size_t)N;
    int k0 = blockIdx.y * 32, n0 = blockIdx.x * 32;
    int tx = threadIdx.x, ty = threadIdx.y;
#pragma unroll
    for (int i = 0; i < 32; i += 8)
        tile[ty + i][tx] = in[(size_t)(k0 + ty + i) * N + (n0 + tx)];
    __syncthreads();
#pragma unroll
    for (int i = 0; i < 32; i += 8) {
        int n = n0 + ty + i;
        float s = sc[n];
        float inv = 1.f / s;                       // s>=tiny by construction
        float v = tile[tx][ty + i];
        float q = rintf(v * inv);
        float l = fminf(127.f, fmaxf(-127.f, rintf((v - q * s) * inv * 256.f)));
        size_t idx = (size_t)n * K + (k0 + tx);
        qh[idx] = (int8_t)q;
        ql[idx] = (int8_t)l;
    }
}

// ---------------- GEMM1: fused SwiGLU up-proj (int8 IMMA) ----------------------
// 512 threads. CTA tile 128m x 64n per B-matrix (w1 & w3 simultaneously).
// warps 0-7 -> w1 tile, warps 8-15 -> w3 tile, each 2m x 4n (warp tile 64x16).
#define S_AH   0
#define S_AL   10240
#define S_B1H  20480
#define S_B1L  25600
#define S_B3H  30720
#define S_B3L  35840
#define G1_STG 40960
#define G1_SMEM (2 * G1_STG)    // 81920

__global__ void __launch_bounds__(512, 1)
gemm1_q(const int8_t* __restrict__ Xqh, const int8_t* __restrict__ Xql,
        const float* __restrict__ sX,
        const int8_t* __restrict__ B1h, const int8_t* __restrict__ B1l,
        const int8_t* __restrict__ B3h, const int8_t* __restrict__ B3l,
        const float* __restrict__ sW1, const float* __restrict__ sW3,
        float* __restrict__ Hf, int routed, int N) {
    const int K = DIM;
    int e = routed ? (int)blockIdx.z : 0;
    int M = routed ? g_cnt[e] : TOK;
    int rowBlock = blockIdx.y * 128;
    if (rowBlock >= M) return;
    int colBlock = blockIdx.x * 64;
    if (routed) {
        size_t wo = (size_t)e * N * K;
        B1h += wo; B1l += wo; B3h += wo; B3l += wo;
        sW1 += (size_t)e * N;  sW3 += (size_t)e * N;
        Hf  += (size_t)e * TOK * N;
    }

    extern __shared__ __align__(16) char smem[];
    uint32_t sb0 = smem_u32(smem);

    int tid = threadIdx.x, lane = tid & 31, warp = tid >> 5;
    int grp = warp >> 3, wm = (warp >> 2) & 1, wn = warp & 3;

    // ---- global->smem mapping ----
    int ra = tid >> 2, ca = tid & 3;              // A: 128 rows x 4 chunks
    bool aval = (rowBlock + ra) < M;
    int  atok = aval ? (routed ? g_idx[e * TOK + rowBlock + ra] : rowBlock + ra) : 0;
    const int8_t* aph = Xqh + (size_t)atok * K + ca * 16;
    const int8_t* apl = Xql + (size_t)atok * K + ca * 16;
    uint32_t adst = (uint32_t)(ra * LDI + ca * 16);

    int rb = (tid >> 2) & 63, cb = tid & 3, bsel = tid >> 8;   // B: 64 rows x 4 chunks
    const int8_t* bph = (bsel ? B3h : B1h) + (size_t)(colBlock + rb) * K + cb * 16;
    const int8_t* bpl = (bsel ? B3l : B1l) + (size_t)(colBlock + rb) * K + cb * 16;
    uint32_t bdsth = (uint32_t)((bsel ? S_B3H : S_B1H) + rb * LDI + cb * 16);
    uint32_t bdstl = (uint32_t)((bsel ? S_B3L : S_B1L) + rb * LDI + cb * 16);

    auto load_stage = [&](int s, int k0) {
        uint32_t sb = sb0 + (uint32_t)s * G1_STG;
        cp16(sb + S_AH + adst, aph + k0, aval);
        cp16(sb + S_AL + adst, apl + k0, aval);
        cp16(sb + bdsth, bph + k0, true);
        cp16(sb + bdstl, bpl + k0, true);
    };

    // ---- ldmatrix addresses ----
    int lrow = lane & 15, lca = (lane >> 4) * 16;
    uint32_t aOffH[4], aOffL[4];
#pragma unroll
    for (int mi = 0; mi < 4; mi++) {
        int r = wm * 64 + mi * 16 + lrow;
        aOffH[mi] = (uint32_t)(S_AH + r * LDI + lca);
        aOffL[mi] = (uint32_t)(S_AL + r * LDI + lca);
    }
    int nloc = (lane & 7) | ((lane & 16) >> 1);
    uint32_t bRow = (uint32_t)((wn * 16 + nloc) * LDI + ((lane >> 3) & 1) * 16);
    uint32_t bOffH = (grp ? S_B3H : S_B1H) + bRow;
    uint32_t bOffL = (grp ? S_B3L : S_B1L) + bRow;

    int hi[4][2][4], cr[4][2][4];
#pragma unroll
    for (int i = 0; i < 4; i++)
#pragma unroll
        for (int j = 0; j < 2; j++)
#pragma unroll
            for (int r = 0; r < 4; r++) { hi[i][j][r] = 0; cr[i][j][r] = 0; }

    load_stage(0, 0);
    CP_COMMIT();
    const int nIter = K / 64;
    for (int i = 0; i < nIter; i++) {
        if (i + 1 < nIter) { load_stage((i + 1) & 1, (i + 1) * 64); CP_COMMIT(); CP_WAIT1(); }
        else               { CP_WAIT0(); }
        __syncthreads();
        uint32_t sb = sb0 + (uint32_t)(i & 1) * G1_STG;
#pragma unroll
        for (int ks = 0; ks < 2; ks++) {
            uint32_t ko = (uint32_t)ks * 32;
            uint32_t ah[4][4], al[4][4];
#pragma unroll
            for (int mi = 0; mi < 4; mi++) {
                LDSM4(ah[mi], sb + aOffH[mi] + ko);
                LDSM4(al[mi], sb + aOffL[mi] + ko);
            }
            uint32_t bh[4], bl[4];
            LDSM4(bh, sb + bOffH + ko);
            LDSM4(bl, sb + bOffL + ko);
#pragma unroll
            for (int mi = 0; mi < 4; mi++)
#pragma unroll
                for (int nf = 0; nf < 2; nf++) {
                    mma_s8(hi[mi][nf], ah[mi], bh[2*nf], bh[2*nf+1]);
                    mma_s8(cr[mi][nf], ah[mi], bl[2*nf], bl[2*nf+1]);
                    mma_s8(cr[mi][nf], al[mi], bh[2*nf], bh[2*nf+1]);
                }
        }
        __syncthreads();
    }

    // ---- epilogue: Cf = sA*sW*(hi + cr/256); silu(C1)*C3 -> Hf fp32 ----
    int rr = lane >> 2, cc = (lane & 3) * 2;
    const float* sWp = grp ? sW3 : sW1;
    float sn[2][2];
#pragma unroll
    for (int nf = 0; nf < 2; nf++) {
        sn[nf][0] = sWp[colBlock + wn * 16 + nf * 8 + cc];
        sn[nf][1] = sWp[colBlock + wn * 16 + nf * 8 + cc + 1];
    }
    float srow[4][2];
#pragma unroll
    for (int mi = 0; mi < 4; mi++)
#pragma unroll
        for (int hf = 0; hf < 2; hf++) {
            int gm = rowBlock + wm * 64 + mi * 16 + rr + hf * 8;
            float sv = 0.f;
            if (gm < M) {
                int tok2 = routed ? g_idx[e * TOK + gm] : gm;
                sv = sX[tok2];
            }
            srow[mi][hf] = sv;
        }
    float cf[4][2][4];
#pragma unroll
    for (int mi = 0; mi < 4; mi++)
#pragma unroll
        for (int nf = 0; nf < 2; nf++)
#pragma unroll
            for (int r = 0; r < 4; r++) {
                float comb = (float)hi[mi][nf][r] + (float)cr[mi][nf][r] * (1.f / 256.f);
                cf[mi][nf][r] = srow[mi][r >> 1] * sn[nf][r & 1] * comb;
            }

    float* exch = reinterpret_cast<float*>(smem);   // 128x64 fp32 exchange
    if (grp == 1) {
#pragma unroll
        for (int mi = 0; mi < 4; mi++)
#pragma unroll
            for (int nf = 0; nf < 2; nf++)
#pragma unroll
                for (int r = 0; r < 4; r++) {
                    int ml = wm * 64 + mi * 16 + rr + (r >> 1) * 8;
                    int nl = wn * 16 + nf * 8 + cc + (r & 1);
                    exch[ml * 64 + nl] = cf[mi][nf][r];
                }
    }
    __syncthreads();
    if (grp == 0) {
#pragma unroll
        for (int mi = 0; mi < 4; mi++)
#pragma unroll
            for (int hf = 0; hf < 2; hf++) {
                int gm = rowBlock + wm * 64 + mi * 16 + rr + hf * 8;
                if (gm >= M) continue;
                int ml = wm * 64 + mi * 16 + rr + hf * 8;
#pragma unroll
                for (int nf = 0; nf < 2; nf++) {
                    int nl = wn * 16 + nf * 8 + cc;
                    float c1a = cf[mi][nf][hf * 2], c1b = cf[mi][nf][hf * 2 + 1];
                    float c3a = exch[ml * 64 + nl], c3b = exch[ml * 64 + nl + 1];
                    float2 hv;
                    hv.x = c1a / (1.f + expf(-c1a)) * c3a;
                    hv.y = c1b / (1.f + expf(-c1b)) * c3b;
                    *reinterpret_cast<float2*>(Hf + (size_t)gm * N + colBlock + nl) = hv;
                }
            }
    }
}

// ---------------- GEMM2: down-projection (int8 IMMA) ---------------------------
// 256 threads. CTA 128m x 64n, warps 2m x 4n (warp tile 64x16).
#define S2_AH  0
#define S2_AL  10240
#define S2_BH  20480
#define S2_BL  25600
#define G2_STG 30720
#define G2_SMEM (2 * G2_STG)    // 61440

__global__ void __launch_bounds__(256, 2)
gemm2_q(const int8_t* __restrict__ Aqh, const int8_t* __restrict__ Aql,
        const float* __restrict__ sA,
        const int8_t* __restrict__ Bqh, const int8_t* __restrict__ Bql,
        const float* __restrict__ sB,
        float* __restrict__ Y, int routed, int K) {
    int e = routed ? (int)blockIdx.z : 0;
    int M = routed ? g_cnt[e] : TOK;
    int rowBlock = blockIdx.y * 128;
    if (rowBlock >= M) return;
    int colBlock = blockIdx.x * 64;
    if (routed) {
        Aqh += (size_t)e * TOK * K;  Aql += (size_t)e * TOK * K;
        sA  += (size_t)e * TOK;
        Bqh += (size_t)e * DIM * K;  Bql += (size_t)e * DIM * K;
        sB  += (size_t)e * DIM;
        Y   += (size_t)e * TOK * DIM;
    }

    extern __shared__ __align__(16) char smem[];
    uint32_t sb0 = smem_u32(smem);

    int tid = threadIdx.x, lane = tid & 31, warp = tid >> 5;
    int wm = warp >> 2, wn = warp & 3;

    int ra = tid >> 2, ca = tid & 3;
    bool av[2];
    const int8_t *aph[2], *apl[2];
    uint32_t ad[2];
#pragma unroll
    for (int j = 0; j < 2; j++) {
        int r = ra + 64 * j;
        av[j] = (rowBlock + r) < M;
        size_t ro = (size_t)(av[j] ? rowBlock + r : 0) * K + ca * 16;
        aph[j] = Aqh + ro;  apl[j] = Aql + ro;
        ad[j] = (uint32_t)(r * LDI + ca * 16);
    }
    const int8_t* bph = Bqh + (size_t)(colBlock + ra) * K + ca * 16;
    const int8_t* bpl = Bql + (size_t)(colBlock + ra) * K + ca * 16;
    uint32_t bd = (uint32_t)(ra * LDI + ca * 16);

    auto load_stage = [&](int s, int k0) {
        uint32_t sb = sb0 + (uint32_t)s * G2_STG;
#pragma unroll
        for (int j = 0; j < 2; j++) {
            cp16(sb + S2_AH + ad[j], aph[j] + k0, av[j]);
            cp16(sb + S2_AL + ad[j], apl[j] + k0, av[j]);
        }
        cp16(sb + S2_BH + bd, bph + k0, true);
        cp16(sb + S2_BL + bd, bpl + k0, true);
    };

    int lrow = lane & 15, lca = (lane >> 4) * 16;
    uint32_t aOffH[4], aOffL[4];
#pragma unroll
    for (int mi = 0; mi < 4; mi++) {
        int r = wm * 64 + mi * 16 + lrow;
        aOffH[mi] = (uint32_t)(S2_AH + r * LDI + lca);
        aOffL[mi] = (uint32_t)(S2_AL + r * LDI + lca);
    }
    int nloc = (lane & 7) | ((lane & 16) >> 1);
    uint32_t bRow = (uint32_t)((wn * 16 + nloc) * LDI + ((lane >> 3) & 1) * 16);
    uint32_t bOffH = S2_BH + bRow, bOffL = S2_BL + bRow;

    int hi[4][2][4], cr[4][2][4];
#pragma unroll
    for (int i = 0; i < 4; i++)
#pragma unroll
        for (int j = 0; j < 2; j++)
#pragma unroll
            for (int r = 0; r < 4; r++) { hi[i][j][r] = 0; cr[i][j][r] = 0; }

    load_stage(0, 0);
    CP_COMMIT();
    const int nIter = K / 64;
    for (int i = 0; i < nIter; i++) {
        if (i + 1 < nIter) { load_stage((i + 1) & 1, (i + 1) * 64); CP_COMMIT(); CP_WAIT1(); }
        else               { CP_WAIT0(); }
        __syncthreads();
        uint32_t sb = sb0 + (uint32_t)(i & 1) * G2_STG;
#pragma unroll
        for (int ks = 0; ks < 2; ks++) {
            uint32_t ko = (uint32_t)ks * 32;
            uint32_t ah[4][4], al[4][4];
#pragma unroll
            for (int mi = 0; mi < 4; mi++) {
                LDSM4(ah[mi], sb + aOffH[mi] + ko);
                LDSM4(al[mi], sb + aOffL[mi] + ko);
            }
            uint32_t bh[4], bl[4];
            LDSM4(bh, sb + bOffH + ko);
            LDSM4(bl, sb + bOffL + ko);
#pragma unroll
            for (int mi = 0; mi < 4; mi++)
#pragma unroll
                for (int nf = 0; nf < 2; nf++) {
                    mma_s8(hi[mi][nf], ah[mi], bh[2*nf], bh[2*nf+1]);
                    mma_s8(cr[mi][nf], ah[mi], bl[2*nf], bl[2*nf+1]);
                    mma_s8(cr[mi][nf], al[mi], bh[2*nf], bh[2*nf+1]);
                }
        }
        __syncthreads();
    }

    int rr = lane >> 2, cc = (lane & 3) * 2;
    float sn[2][2];
#pragma unroll
    for (int nf = 0; nf < 2; nf++) {
        sn[nf][0] = sB[colBlock + wn * 16 + nf * 8 + cc];
        sn[nf][1] = sB[colBlock + wn * 16 + nf * 8 + cc + 1];
    }
#pragma unroll
    for (int mi = 0; mi < 4; mi++)
#pragma unroll
        for (int hf = 0; hf < 2; hf++) {
            int gm = rowBlock + wm * 64 + mi * 16 + rr + hf * 8;
            if (gm >= M) continue;
            float sr = sA[gm];
            float w  = routed ? g_wgt[e * TOK + gm] : 1.0f;
            float sw = sr * w;
            float* dst = Y + (size_t)gm * DIM;
#pragma unroll
            for (int nf = 0; nf < 2; nf++) {
                int col = colBlock + wn * 16 + nf * 8 + cc;
                float2 v;
                v.x = sw * sn[nf][0] * ((float)hi[mi][nf][hf*2]   + (float)cr[mi][nf][hf*2]   * (1.f/256.f));
                v.y = sw * sn[nf][1] * ((float)hi[mi][nf][hf*2+1] + (float)cr[mi][nf][hf*2+1] * (1.f/256.f));
                *reinterpret_cast<float2*>(dst + col) = v;
            }
        }
}

// out[t] += yp[slot0(t)] + yp[slot1(t)]
__global__ void combine_kernel(float* __restrict__ out) {
    int t = blockIdx.x;
    int d = threadIdx.x;
    int s0 = g_slot[2 * t], s1 = g_slot[2 * t + 1];
    float4* o = reinterpret_cast<float4*>(out) + (size_t)t * 256 + d;
    const float4 a  = *o;
    const float4 b0 = reinterpret_cast<const float4*>(g_yp)[(size_t)s0 * 256 + d];
    const float4 b1 = reinterpret_cast<const float4*>(g_yp)[(size_t)s1 * 256 + d];
    float4 r;
    r.x = a.x + (b0.x + b1.x);
    r.y = a.y + (b0.y + b1.y);
    r.z = a.z + (b0.z + b1.z);
    r.w = a.w + (b0.w + b1.w);
    *o = r;
}

// ---------------- launcher -----------------------------------------------------
extern "C" void kernel_launch(void* const* d_in, const int* in_sizes, int n_in,
                              void* d_out, int out_size) {
    const float* x   = (const float*)d_in[0];
    const float* gw  = (const float*)d_in[1];
    const float* w1  = (const float*)d_in[2];
    const float* w2  = (const float*)d_in[3];
    const float* w3  = (const float*)d_in[4];
    const float* sw1 = (const float*)d_in[5];
    const float* sw2 = (const float*)d_in[6];
    const float* sw3 = (const float*)d_in[7];
    float* out = (float*)d_out;
    (void)in_sizes; (void)n_in; (void)out_size;

    cudaFuncSetAttribute(gemm1_q, cudaFuncAttributeMaxDynamicSharedMemorySize, G1_SMEM);
    cudaFuncSetAttribute(gemm2_q, cudaFuncAttributeMaxDynamicSharedMemorySize, G2_SMEM);

    int8_t *xqh, *xql, *w1qh, *w1ql, *w3qh, *w3ql, *w2qh, *w2ql;
    int8_t *s1qh, *s1ql, *s3qh, *s3ql, *s2qh, *s2ql;
    int8_t *hqh, *hql, *hsqh, *hsql;
    float *sx, *sw1s, *sw3s, *sw2s, *ss1, *ss3, *ss2, *hf, *hsf, *sh, *shs, *yp;
    cudaGetSymbolAddress((void**)&xqh, g_xqh);   cudaGetSymbolAddress((void**)&xql, g_xql);
    cudaGetSymbolAddress((void**)&sx,  g_sx);
    cudaGetSymbolAddress((void**)&w1qh, g_w1qh); cudaGetSymbolAddress((void**)&w1ql, g_w1ql);
    cudaGetSymbolAddress((void**)&w3qh, g_w3qh); cudaGetSymbolAddress((void**)&w3ql, g_w3ql);
    cudaGetSymbolAddress((void**)&w2qh, g_w2qh); cudaGetSymbolAddress((void**)&w2ql, g_w2ql);
    cudaGetSymbolAddress((void**)&sw1s, g_sw1);  cudaGetSymbolAddress((void**)&sw3s, g_sw3);
    cudaGetSymbolAddress((void**)&sw2s, g_sw2);
    cudaGetSymbolAddress((void**)&s1qh, g_s1qh); cudaGetSymbolAddress((void**)&s1ql, g_s1ql);
    cudaGetSymbolAddress((void**)&s3qh, g_s3qh); cudaGetSymbolAddress((void**)&s3ql, g_s3ql);
    cudaGetSymbolAddress((void**)&s2qh, g_s2qh); cudaGetSymbolAddress((void**)&s2ql, g_s2ql);
    cudaGetSymbolAddress((void**)&ss1, g_ss1);   cudaGetSymbolAddress((void**)&ss3, g_ss3);
    cudaGetSymbolAddress((void**)&ss2, g_ss2);
    cudaGetSymbolAddress((void**)&hf,  g_hf);    cudaGetSymbolAddress((void**)&hsf, g_hsf);
    cudaGetSymbolAddress((void**)&hqh, g_hqh);   cudaGetSymbolAddress((void**)&hql, g_hql);
    cudaGetSymbolAddress((void**)&hsqh, g_hsqh); cudaGetSymbolAddress((void**)&hsql, g_hsql);
    cudaGetSymbolAddress((void**)&sh,  g_sh);    cudaGetSymbolAddress((void**)&shs, g_shs);
    cudaGetSymbolAddress((void**)&yp,  g_yp);

    zero_counts_kernel<<<1, 32>>>();
    gate_kernel<<<TOK / 8, 256>>>(x, gw);
    quant_rows_kernel<<<TOK, 256>>>(x, xqh, xql, sx, DIM, 0);

    // weight conversion: colmax -> transpose+quantize
    colmax_kernel<<<dim3(EHID / 256, NEXP), 256>>>(w1, sw1s, DIM, EHID);
    cvtTq_kernel<<<dim3(EHID / 32, DIM / 32, NEXP), dim3(32, 8)>>>(w1, sw1s, w1qh, w1ql, DIM, EHID);
    colmax_kernel<<<dim3(EHID / 256, NEXP), 256>>>(w3, sw3s, DIM, EHID);
    cvtTq_kernel<<<dim3(EHID / 32, DIM / 32, NEXP), dim3(32, 8)>>>(w3, sw3s, w3qh, w3ql, DIM, EHID);
    colmax_kernel<<<dim3(DIM / 256, NEXP), 256>>>(w2, sw2s, EHID, DIM);
    cvtTq_kernel<<<dim3(DIM / 32, EHID / 32, NEXP), dim3(32, 8)>>>(w2, sw2s, w2qh, w2ql, EHID, DIM);
    colmax_kernel<<<dim3(SHID / 256, 1), 256>>>(sw1, ss1, DIM, SHID);
    cvtTq_kernel<<<dim3(SHID / 32, DIM / 32, 1), dim3(32, 8)>>>(sw1, ss1, s1qh, s1ql, DIM, SHID);
    colmax_kernel<<<dim3(SHID / 256, 1), 256>>>(sw3, ss3, DIM, SHID);
    cvtTq_kernel<<<dim3(SHID / 32, DIM / 32, 1), dim3(32, 8)>>>(sw3, ss3, s3qh, s3ql, DIM, SHID);
    colmax_kernel<<<dim3(DIM / 256, 1), 256>>>(sw2, ss2, SHID, DIM);
    cvtTq_kernel<<<dim3(DIM / 32, SHID / 32, 1), dim3(32, 8)>>>(sw2, ss2, s2qh, s2ql, SHID, DIM);

    // shared expert (initializes d_out)
    gemm1_q<<<dim3(SHID / 64, TOK / 128, 1), 512, G1_SMEM>>>(
        xqh, xql, sx, s1qh, s1ql, s3qh, s3ql, ss1, ss3, hsf, 0, SHID);
    quant_rows_kernel<<<TOK, 256>>>(hsf, hsqh, hsql, shs, SHID, 0);
    gemm2_q<<<dim3(DIM / 64, TOK / 128, 1), 256, G2_SMEM>>>(
        hsqh, hsql, shs, s2qh, s2ql, ss2, out, 0, SHID);

    // routed experts
    gemm1_q<<<dim3(EHID / 64, TOK / 128, NEXP), 512, G1_SMEM>>>(
        xqh, xql, sx, w1qh, w1ql, w3qh, w3ql, sw1s, sw3s, hf, 1, EHID);
    quant_rows_kernel<<<NEXP * TOK, 256>>>(hf, hqh, hql, sh, EHID, 1);
    gemm2_q<<<dim3(DIM / 64, TOK / 128, NEXP), 256, G2_SMEM>>>(
        hqh, hql, sh, w2qh, w2ql, sw2s, yp, 1, EHID);

    combine_kernel<<<TOK, 256>>>(out);
}

// round 6
// speedup vs baseline: 3.6497x; 3.6497x over previous
#include <cuda_runtime.h>
#include <cuda_fp16.h>
#include <math.h>
#include <stdint.h>

#define TOK   4096
#define DIM   1024
#define NEXP  8
#define EHID  2816
#define SHID  1536
#define LDH   40      // smem row stride in fp16 elems (32 data + 8 pad)

typedef __half fp16;

// ---------------- scratch (device globals) ----------------------------------
__device__ fp16  g_xh [(size_t)TOK*DIM];
__device__ fp16  g_xl [(size_t)TOK*DIM];
__device__ fp16  g_w1h[(size_t)NEXP*EHID*DIM];
__device__ fp16  g_w3h[(size_t)NEXP*EHID*DIM];
__device__ fp16  g_w2h[(size_t)NEXP*DIM*EHID];
__device__ fp16  g_s1h[(size_t)SHID*DIM];
__device__ fp16  g_s3h[(size_t)SHID*DIM];
__device__ fp16  g_s2h[(size_t)DIM*SHID];
__device__ fp16  g_hh [(size_t)NEXP*TOK*EHID];
__device__ fp16  g_hl [(size_t)NEXP*TOK*EHID];
__device__ fp16  g_hsh[(size_t)TOK*SHID];
__device__ fp16  g_hsl[(size_t)TOK*SHID];
__device__ float g_yp [(size_t)NEXP*TOK*DIM];
__device__ int   g_cnt[NEXP];
__device__ int   g_idx[NEXP*TOK];
__device__ float g_wgt[NEXP*TOK];
__device__ int   g_slot[TOK*2];

// ---------------- helpers ----------------------------------------------------
__device__ __forceinline__ uint32_t smem_u32(const void* p) {
    uint32_t a;
    asm("{ .reg .u64 t; cvta.to.shared.u64 t, %1; cvt.u32.u64 %0, t; }"
        : "=r"(a) : "l"(p));
    return a;
}
__device__ __forceinline__ void cp16(uint32_t saddr, const void* g, bool valid) {
    int sz = valid ? 16 : 0;
    asm volatile("cp.async.cg.shared.global [%0], [%1], 16, %2;"
                 :: "r"(saddr), "l"(g), "r"(sz));
}
#define CP_COMMIT() asm volatile("cp.async.commit_group;")
#define CP_WAIT1()  asm volatile("cp.async.wait_group 1;")
#define CP_WAIT0()  asm volatile("cp.async.wait_group 0;")

#define LDSM4(r, addr) \
    asm volatile("ldmatrix.sync.aligned.m8n8.x4.shared.b16 {%0,%1,%2,%3}, [%4];" \
        : "=r"((r)[0]), "=r"((r)[1]), "=r"((r)[2]), "=r"((r)[3]) : "r"(addr))

__device__ __forceinline__ void mma_f16(float d[4], const uint32_t a[4],
                                        uint32_t b0, uint32_t b1) {
    asm volatile(
        "mma.sync.aligned.m16n8k16.row.col.f32.f16.f16.f32 "
        "{%0,%1,%2,%3},{%4,%5,%6,%7},{%8,%9},{%0,%1,%2,%3};"
        : "+f"(d[0]), "+f"(d[1]), "+f"(d[2]), "+f"(d[3])
        : "r"(a[0]), "r"(a[1]), "r"(a[2]), "r"(a[3]), "r"(b0), "r"(b1));
}

__device__ __forceinline__ uint32_t pack2(fp16 a, fp16 b) {
    return ((uint32_t)__half_as_ushort(b) << 16) | (uint32_t)__half_as_ushort(a);
}

// ---------------- small kernels ------------------------------------------------
__global__ void zero_counts_kernel() {
    if (threadIdx.x < NEXP) g_cnt[threadIdx.x] = 0;
}

// x -> (hi fp16, lo fp16)
__global__ void cvtx_kernel(const float* __restrict__ in,
                            fp16* __restrict__ oh, fp16* __restrict__ ol, int n4) {
    int i = blockIdx.x * blockDim.x + threadIdx.x;
    if (i >= n4) return;
    float4 v = reinterpret_cast<const float4*>(in)[i];
    fp16 h0 = __float2half(v.x), h1 = __float2half(v.y);
    fp16 h2 = __float2half(v.z), h3 = __float2half(v.w);
    fp16 l0 = __float2half(v.x - __half2float(h0));
    fp16 l1 = __float2half(v.y - __half2float(h1));
    fp16 l2 = __float2half(v.z - __half2float(h2));
    fp16 l3 = __float2half(v.w - __half2float(h3));
    uint2 ph; ph.x = pack2(h0, h1); ph.y = pack2(h2, h3);
    uint2 pl; pl.x = pack2(l0, l1); pl.y = pack2(l2, l3);
    reinterpret_cast<uint2*>(oh)[i] = ph;
    reinterpret_cast<uint2*>(ol)[i] = pl;
}

// transpose+convert: in [z][K][N] fp32 -> oh [z][N][K] fp16 (hi only)
__global__ void cvtT_kernel(const float* __restrict__ in,
                            fp16* __restrict__ oh, int K, int N) {
    __shared__ float tile[32][33];
    size_t z = blockIdx.z;
    in += z * (size_t)K * N;
    oh += z * (size_t)N * K;
    int k0 = blockIdx.y * 32, n0 = blockIdx.x * 32;
    int tx = threadIdx.x, ty = threadIdx.y;
#pragma unroll
    for (int i = 0; i < 32; i += 8)
        tile[ty + i][tx] = in[(size_t)(k0 + ty + i) * N + (n0 + tx)];
    __syncthreads();
#pragma unroll
    for (int i = 0; i < 32; i += 8)
        oh[(size_t)(n0 + ty + i) * K + (k0 + tx)] = __float2half(tile[tx][ty + i]);
}

__global__ void gate_kernel(const float* __restrict__ x, const float* __restrict__ gw) {
    int tok  = (blockIdx.x * blockDim.x + threadIdx.x) >> 5;
    int lane = threadIdx.x & 31;
    if (tok >= TOK) return;
    const float* xr = x + (size_t)tok * DIM;
    float acc[NEXP];
#pragma unroll
    for (int e = 0; e < NEXP; e++) acc[e] = 0.f;
    for (int d = lane; d < DIM; d += 32) {
        float xv = xr[d];
#pragma unroll
        for (int e = 0; e < NEXP; e++) acc[e] = fmaf(xv, gw[e * DIM + d], acc[e]);
    }
#pragma unroll
    for (int e = 0; e < NEXP; e++)
#pragma unroll
        for (int off = 16; off > 0; off >>= 1)
            acc[e] += __shfl_xor_sync(0xffffffffu, acc[e], off);
    if (lane == 0) {
        float mx = acc[0];
#pragma unroll
        for (int e = 1; e < NEXP; e++) mx = fmaxf(mx, acc[e]);
        float p[NEXP], s = 0.f;
#pragma unroll
        for (int e = 0; e < NEXP; e++) { p[e] = expf(acc[e] - mx); s += p[e]; }
        float inv = 1.f / s;
#pragma unroll
        for (int e = 0; e < NEXP; e++) p[e] *= inv;
        int i1 = 0;
#pragma unroll
        for (int e = 1; e < NEXP; e++) if (p[e] > p[i1]) i1 = e;
        int i2 = (i1 == 0) ? 1 : 0;
#pragma unroll
        for (int e = 0; e < NEXP; e++) if (e != i1 && p[e] > p[i2]) i2 = e;
        int pos1 = atomicAdd(&g_cnt[i1], 1);
        g_idx[i1 * TOK + pos1] = tok;  g_wgt[i1 * TOK + pos1] = p[i1];
        g_slot[2 * tok] = i1 * TOK + pos1;
        int pos2 = atomicAdd(&g_cnt[i2], 1);
        g_idx[i2 * TOK + pos2] = tok;  g_wgt[i2 * TOK + pos2] = p[i2];
        g_slot[2 * tok + 1] = i2 * TOK + pos2;
    }
}

// ---------------- GEMM1: fused SwiGLU up-proj (fp16 2-term) --------------------
// BM=128, BN=64 per B-matrix, BK=32, 256 threads (8 warps: 2m x 4n).
// Stage (fp16 elems): Ah[128*40] Al[128*40] B1h[64*40] B3h[64*40]
#define G1_S_AH   0
#define G1_S_AL   5120
#define G1_S_B1H  10240
#define G1_S_B3H  12800
#define G1_STG    15360
#define G1_SMEM   (2 * G1_STG * 2)   // 61440 B

__global__ void __launch_bounds__(256, 2)
gemm1_kernel(const fp16* __restrict__ Xh, const fp16* __restrict__ Xl,
             const fp16* __restrict__ B1h, const fp16* __restrict__ B3h,
             fp16* __restrict__ Hh, fp16* __restrict__ Hl,
             int routed, int N) {
    const int K = DIM;
    int e = routed ? (int)blockIdx.z : 0;
    int M = routed ? g_cnt[e] : TOK;
    int rowBlock = blockIdx.y * 128;
    if (rowBlock >= M) return;
    int colBlock = blockIdx.x * 64;
    if (routed) {
        size_t wo = (size_t)e * N * K;
        B1h += wo; B3h += wo;
        Hh += (size_t)e * TOK * N;  Hl += (size_t)e * TOK * N;
    }

    extern __shared__ __align__(16) fp16 sm1[];
    uint32_t sb0 = smem_u32(sm1);

    int tid = threadIdx.x, lane = tid & 31, warp = tid >> 5;
    int wm = warp >> 2, wn = warp & 3;

    // ---- global load mapping ----
    int ra = tid >> 1, ka = (tid & 1) * 16;       // A: 2 thr/row, 16 halves each
    bool aval = (rowBlock + ra) < M;
    int asrc = aval ? (routed ? g_idx[e * TOK + rowBlock + ra] : rowBlock + ra) : 0;
    const fp16* aph = Xh + (size_t)asrc * K + ka;
    const fp16* apl = Xl + (size_t)asrc * K + ka;
    uint32_t adst = (uint32_t)(ra * LDH + ka) * 2;

    int rb = tid >> 2, kb = (tid & 3) * 8;        // B: 4 thr/row, 8 halves each
    const fp16* b1p = B1h + (size_t)(colBlock + rb) * K + kb;
    const fp16* b3p = B3h + (size_t)(colBlock + rb) * K + kb;
    uint32_t bdst = (uint32_t)(rb * LDH + kb) * 2;

    auto load_stage = [&](int s, int k0) {
        uint32_t sb = sb0 + (uint32_t)s * G1_STG * 2;
        cp16(sb + G1_S_AH * 2 + adst,      aph + k0,     aval);
        cp16(sb + G1_S_AH * 2 + adst + 16, aph + k0 + 8, aval);
        cp16(sb + G1_S_AL * 2 + adst,      apl + k0,     aval);
        cp16(sb + G1_S_AL * 2 + adst + 16, apl + k0 + 8, aval);
        cp16(sb + G1_S_B1H * 2 + bdst, b1p + k0, true);
        cp16(sb + G1_S_B3H * 2 + bdst, b3p + k0, true);
    };

    // ---- ldmatrix bases ----
    int lrow = lane & 15, lkA = (lane >> 4) * 8;
    uint32_t aOffH[4], aOffL[4];
#pragma unroll
    for (int mi = 0; mi < 4; mi++) {
        int r = wm * 64 + mi * 16 + lrow;
        aOffH[mi] = (uint32_t)(G1_S_AH + r * LDH + lkA) * 2;
        aOffL[mi] = (uint32_t)(G1_S_AL + r * LDH + lkA) * 2;
    }
    int nloc = (lane & 7) | ((lane & 16) >> 1);
    int lkB  = ((lane >> 3) & 1) * 8;
    uint32_t bRow = (uint32_t)((wn * 16 + nloc) * LDH + lkB) * 2;
    uint32_t b1Off = G1_S_B1H * 2 + bRow;
    uint32_t b3Off = G1_S_B3H * 2 + bRow;

    float acc1[4][2][4], acc3[4][2][4];
#pragma unroll
    for (int i = 0; i < 4; i++)
#pragma unroll
        for (int j = 0; j < 2; j++)
#pragma unroll
            for (int r = 0; r < 4; r++) { acc1[i][j][r] = 0.f; acc3[i][j][r] = 0.f; }

    load_stage(0, 0);
    CP_COMMIT();
    const int nIter = K / 32;
    for (int i = 0; i < nIter; i++) {
        if (i + 1 < nIter) { load_stage((i + 1) & 1, (i + 1) * 32); CP_COMMIT(); CP_WAIT1(); }
        else               { CP_WAIT0(); }
        __syncthreads();
        uint32_t sb = sb0 + (uint32_t)(i & 1) * G1_STG * 2;
#pragma unroll
        for (int ks = 0; ks < 2; ks++) {
            uint32_t ko = (uint32_t)ks * 32;   // 16 halves = 32 bytes
            uint32_t ah[4][4], al[4][4];
#pragma unroll
            for (int mi = 0; mi < 4; mi++) {
                LDSM4(ah[mi], sb + aOffH[mi] + ko);
                LDSM4(al[mi], sb + aOffL[mi] + ko);
            }
            uint32_t b1[4], b3[4];
            LDSM4(b1, sb + b1Off + ko);
            LDSM4(b3, sb + b3Off + ko);
#pragma unroll
            for (int mi = 0; mi < 4; mi++)
#pragma unroll
                for (int nf = 0; nf < 2; nf++) {
                    mma_f16(acc1[mi][nf], ah[mi], b1[2*nf], b1[2*nf+1]);
                    mma_f16(acc1[mi][nf], al[mi], b1[2*nf], b1[2*nf+1]);
                    mma_f16(acc3[mi][nf], ah[mi], b3[2*nf], b3[2*nf+1]);
                    mma_f16(acc3[mi][nf], al[mi], b3[2*nf], b3[2*nf+1]);
                }
        }
        __syncthreads();
    }

    // ---- epilogue: silu(acc1)*acc3, split hi/lo fp16, store ----
    int rr = lane >> 2, cc = (lane & 3) * 2;
#pragma unroll
    for (int mi = 0; mi < 4; mi++) {
        int gmb = rowBlock + wm * 64 + mi * 16 + rr;
#pragma unroll
        for (int nf = 0; nf < 2; nf++) {
            int col = colBlock + wn * 16 + nf * 8 + cc;
#pragma unroll
            for (int hf = 0; hf < 2; hf++) {
                int gm = gmb + hf * 8;
                if (gm < M) {
                    float v1a = acc1[mi][nf][hf*2], v1b = acc1[mi][nf][hf*2+1];
                    float v3a = acc3[mi][nf][hf*2], v3b = acc3[mi][nf][hf*2+1];
                    float h0 = v1a / (1.f + expf(-v1a)) * v3a;
                    float h1 = v1b / (1.f + expf(-v1b)) * v3b;
                    fp16 hh0 = __float2half(h0), hh1 = __float2half(h1);
                    fp16 ll0 = __float2half(h0 - __half2float(hh0));
                    fp16 ll1 = __float2half(h1 - __half2float(hh1));
                    *reinterpret_cast<uint32_t*>(Hh + (size_t)gm * N + col) = pack2(hh0, hh1);
                    *reinterpret_cast<uint32_t*>(Hl + (size_t)gm * N + col) = pack2(ll0, ll1);
                }
            }
        }
    }
}

// ---------------- GEMM2: down-projection (fp16 2-term) -------------------------
// BM=128, BN=64, BK=32, 256 threads (8 warps: 2m x 4n, warp tile 64x16).
#define G2_S_AH  0
#define G2_S_AL  5120
#define G2_S_BH  10240
#define G2_STG   12800
#define G2_SMEM  (2 * G2_STG * 2)    // 51200 B

__global__ void __launch_bounds__(256, 2)
gemm2_kernel(const fp16* __restrict__ Ah, const fp16* __restrict__ Al,
             const fp16* __restrict__ Bh,
             float* __restrict__ Y, int routed, int K) {
    int e = routed ? (int)blockIdx.z : 0;
    int M = routed ? g_cnt[e] : TOK;
    int rowBlock = blockIdx.y * 128;
    if (rowBlock >= M) return;
    int colBlock = blockIdx.x * 64;
    if (routed) {
        Ah += (size_t)e * TOK * K;  Al += (size_t)e * TOK * K;
        Bh += (size_t)e * DIM * K;
        Y  += (size_t)e * TOK * DIM;
    }

    extern __shared__ __align__(16) fp16 sm2[];
    uint32_t sb0 = smem_u32(sm2);

    int tid = threadIdx.x, lane = tid & 31, warp = tid >> 5;
    int wm = warp >> 2, wn = warp & 3;

    int ra = tid >> 1, ka = (tid & 1) * 16;
    bool aval = (rowBlock + ra) < M;
    const fp16* aph = Ah + (size_t)(aval ? rowBlock + ra : 0) * K + ka;
    const fp16* apl = Al + (size_t)(aval ? rowBlock + ra : 0) * K + ka;
    uint32_t adst = (uint32_t)(ra * LDH + ka) * 2;

    int rb = tid >> 2, kb = (tid & 3) * 8;
    const fp16* bp = Bh + (size_t)(colBlock + rb) * K + kb;
    uint32_t bdst = (uint32_t)(rb * LDH + kb) * 2;

    auto load_stage = [&](int s, int k0) {
        uint32_t sb = sb0 + (uint32_t)s * G2_STG * 2;
        cp16(sb + G2_S_AH * 2 + adst,      aph + k0,     aval);
        cp16(sb + G2_S_AH * 2 + adst + 16, aph + k0 + 8, aval);
        cp16(sb + G2_S_AL * 2 + adst,      apl + k0,     aval);
        cp16(sb + G2_S_AL * 2 + adst + 16, apl + k0 + 8, aval);
        cp16(sb + G2_S_BH * 2 + bdst, bp + k0, true);
    };

    int lrow = lane & 15, lkA = (lane >> 4) * 8;
    uint32_t aOffH[4], aOffL[4];
#pragma unroll
    for (int mi = 0; mi < 4; mi++) {
        int r = wm * 64 + mi * 16 + lrow;
        aOffH[mi] = (uint32_t)(G2_S_AH + r * LDH + lkA) * 2;
        aOffL[mi] = (uint32_t)(G2_S_AL + r * LDH + lkA) * 2;
    }
    int nloc = (lane & 7) | ((lane & 16) >> 1);
    int lkB  = ((lane >> 3) & 1) * 8;
    uint32_t bOff = (uint32_t)(G2_S_BH + (wn * 16 + nloc) * LDH + lkB) * 2;

    float acc[4][2][4];
#pragma unroll
    for (int i = 0; i < 4; i++)
#pragma unroll
        for (int j = 0; j < 2; j++)
#pragma unroll
            for (int r = 0; r < 4; r++) acc[i][j][r] = 0.f;

    load_stage(0, 0);
    CP_COMMIT();
    const int nIter = K / 32;
    for (int i = 0; i < nIter; i++) {
        if (i + 1 < nIter) { load_stage((i + 1) & 1, (i + 1) * 32); CP_COMMIT(); CP_WAIT1(); }
        else               { CP_WAIT0(); }
        __syncthreads();
        uint32_t sb = sb0 + (uint32_t)(i & 1) * G2_STG * 2;
#pragma unroll
        for (int ks = 0; ks < 2; ks++) {
            uint32_t ko = (uint32_t)ks * 32;
            uint32_t ah[4][4], al[4][4];
#pragma unroll
            for (int mi = 0; mi < 4; mi++) {
                LDSM4(ah[mi], sb + aOffH[mi] + ko);
                LDSM4(al[mi], sb + aOffL[mi] + ko);
            }
            uint32_t b[4];
            LDSM4(b, sb + bOff + ko);
#pragma unroll
            for (int mi = 0; mi < 4; mi++)
#pragma unroll
                for (int nf = 0; nf < 2; nf++) {
                    mma_f16(acc[mi][nf], ah[mi], b[2*nf], b[2*nf+1]);
                    mma_f16(acc[mi][nf], al[mi], b[2*nf], b[2*nf+1]);
                }
        }
        __syncthreads();
    }

    int rr = lane >> 2, cc = (lane & 3) * 2;
#pragma unroll
    for (int mi = 0; mi < 4; mi++) {
        int gmb = rowBlock + wm * 64 + mi * 16 + rr;
#pragma unroll
        for (int hf = 0; hf < 2; hf++) {
            int gm = gmb + hf * 8;
            if (gm < M) {
                float w = routed ? g_wgt[e * TOK + gm] : 1.0f;
                float* dst = Y + (size_t)gm * DIM;
#pragma unroll
                for (int nf = 0; nf < 2; nf++) {
                    int col = colBlock + wn * 16 + nf * 8 + cc;
                    float2 v;
                    v.x = w * acc[mi][nf][hf*2];
                    v.y = w * acc[mi][nf][hf*2+1];
                    *reinterpret_cast<float2*>(dst + col) = v;
                }
            }
        }
    }
}

// out[t] += yp[slot0(t)] + yp[slot1(t)]
__global__ void combine_kernel(float* __restrict__ out) {
    int t = blockIdx.x;
    int d = threadIdx.x;
    int s0 = g_slot[2 * t], s1 = g_slot[2 * t + 1];
    float4* o = reinterpret_cast<float4*>(out) + (size_t)t * 256 + d;
    const float4 a  = *o;
    const float4 b0 = reinterpret_cast<const float4*>(g_yp)[(size_t)s0 * 256 + d];
    const float4 b1 = reinterpret_cast<const float4*>(g_yp)[(size_t)s1 * 256 + d];
    float4 r;
    r.x = a.x + (b0.x + b1.x);
    r.y = a.y + (b0.y + b1.y);
    r.z = a.z + (b0.z + b1.z);
    r.w = a.w + (b0.w + b1.w);
    *o = r;
}

// ---------------- launcher -----------------------------------------------------
extern "C" void kernel_launch(void* const* d_in, const int* in_sizes, int n_in,
                              void* d_out, int out_size) {
    const float* x   = (const float*)d_in[0];
    const float* gw  = (const float*)d_in[1];
    const float* w1  = (const float*)d_in[2];
    const float* w2  = (const float*)d_in[3];
    const float* w3  = (const float*)d_in[4];
    const float* sw1 = (const float*)d_in[5];
    const float* sw2 = (const float*)d_in[6];
    const float* sw3 = (const float*)d_in[7];
    float* out = (float*)d_out;
    (void)in_sizes; (void)n_in; (void)out_size;

    cudaFuncSetAttribute(gemm1_kernel, cudaFuncAttributeMaxDynamicSharedMemorySize, G1_SMEM);
    cudaFuncSetAttribute(gemm2_kernel, cudaFuncAttributeMaxDynamicSharedMemorySize, G2_SMEM);

    fp16 *xh, *xl, *w1h, *w3h, *w2h, *s1h, *s3h, *s2h, *hh, *hl, *hsh, *hsl;
    float* yp;
    cudaGetSymbolAddress((void**)&xh,  g_xh);  cudaGetSymbolAddress((void**)&xl,  g_xl);
    cudaGetSymbolAddress((void**)&w1h, g_w1h); cudaGetSymbolAddress((void**)&w3h, g_w3h);
    cudaGetSymbolAddress((void**)&w2h, g_w2h);
    cudaGetSymbolAddress((void**)&s1h, g_s1h); cudaGetSymbolAddress((void**)&s3h, g_s3h);
    cudaGetSymbolAddress((void**)&s2h, g_s2h);
    cudaGetSymbolAddress((void**)&hh,  g_hh);  cudaGetSymbolAddress((void**)&hl,  g_hl);
    cudaGetSymbolAddress((void**)&hsh, g_hsh); cudaGetSymbolAddress((void**)&hsl, g_hsl);
    cudaGetSymbolAddress((void**)&yp,  g_yp);

    zero_counts_kernel<<<1, 32>>>();
    cvtx_kernel<<<(TOK * DIM / 4 + 255) / 256, 256>>>(x, xh, xl, TOK * DIM / 4);
    cvtT_kernel<<<dim3(EHID / 32, DIM / 32, NEXP), dim3(32, 8)>>>(w1, w1h, DIM, EHID);
    cvtT_kernel<<<dim3(EHID / 32, DIM / 32, NEXP), dim3(32, 8)>>>(w3, w3h, DIM, EHID);
    cvtT_kernel<<<dim3(DIM / 32, EHID / 32, NEXP), dim3(32, 8)>>>(w2, w2h, EHID, DIM);
    cvtT_kernel<<<dim3(SHID / 32, DIM / 32, 1),  dim3(32, 8)>>>(sw1, s1h, DIM, SHID);
    cvtT_kernel<<<dim3(SHID / 32, DIM / 32, 1),  dim3(32, 8)>>>(sw3, s3h, DIM, SHID);
    cvtT_kernel<<<dim3(DIM / 32, SHID / 32, 1),  dim3(32, 8)>>>(sw2, s2h, SHID, DIM);
    gate_kernel<<<TOK / 8, 256>>>(x, gw);

    // shared expert (initializes d_out)
    gemm1_kernel<<<dim3(SHID / 64, TOK / 128, 1), 256, G1_SMEM>>>(
        xh, xl, s1h, s3h, hsh, hsl, 0, SHID);
    gemm2_kernel<<<dim3(DIM / 64, TOK / 128, 1), 256, G2_SMEM>>>(
        hsh, hsl, s2h, out, 0, SHID);

    // routed experts, batched over grid.z
    gemm1_kernel<<<dim3(EHID / 64, TOK / 128, NEXP), 256, G1_SMEM>>>(
        xh, xl, w1h, w3h, hh, hl, 1, EHID);
    gemm2_kernel<<<dim3(DIM / 64, TOK / 128, NEXP), 256, G2_SMEM>>>(
        hh, hl, w2h, yp, 1, EHID);

    combine_kernel<<<TOK, 256>>>(out);
}

// round 7
// speedup vs baseline: 4.4902x; 1.2303x over previous
#include <cuda_runtime.h>
#include <cuda_fp16.h>
#include <math.h>
#include <stdint.h>

#define TOK   4096
#define DIM   1024
#define NEXP  8
#define EHID  2816
#define SHID  1536
#define LDH   40      // smem row stride in fp16 elems (32 data + 8 pad)

typedef __half fp16;

// ---------------- scratch (device globals) ----------------------------------
__device__ fp16  g_xh [(size_t)TOK*DIM];
__device__ fp16  g_xl [(size_t)TOK*DIM];
__device__ fp16  g_w1h[(size_t)NEXP*EHID*DIM];
__device__ fp16  g_w3h[(size_t)NEXP*EHID*DIM];
__device__ fp16  g_w2h[(size_t)NEXP*DIM*EHID];
__device__ fp16  g_s1h[(size_t)SHID*DIM];
__device__ fp16  g_s3h[(size_t)SHID*DIM];
__device__ fp16  g_s2h[(size_t)DIM*SHID];
__device__ fp16  g_hh [(size_t)NEXP*TOK*EHID];   // routed hidden (fp16 hi only)
__device__ fp16  g_hsh[(size_t)TOK*SHID];        // shared hidden
__device__ float g_yp [(size_t)NEXP*TOK*DIM];
__device__ int   g_cnt[NEXP];
__device__ int   g_idx[NEXP*TOK];
__device__ float g_wgt[NEXP*TOK];
__device__ int   g_slot[TOK*2];

// ---------------- helpers ----------------------------------------------------
__device__ __forceinline__ uint32_t smem_u32(const void* p) {
    uint32_t a;
    asm("{ .reg .u64 t; cvta.to.shared.u64 t, %1; cvt.u32.u64 %0, t; }"
        : "=r"(a) : "l"(p));
    return a;
}
__device__ __forceinline__ void cp16(uint32_t saddr, const void* g, bool valid) {
    int sz = valid ? 16 : 0;
    asm volatile("cp.async.cg.shared.global [%0], [%1], 16, %2;"
                 :: "r"(saddr), "l"(g), "r"(sz));
}
#define CP_COMMIT() asm volatile("cp.async.commit_group;")
#define CP_WAIT1()  asm volatile("cp.async.wait_group 1;")
#define CP_WAIT0()  asm volatile("cp.async.wait_group 0;")

#define LDSM4(r, addr) \
    asm volatile("ldmatrix.sync.aligned.m8n8.x4.shared.b16 {%0,%1,%2,%3}, [%4];" \
        : "=r"((r)[0]), "=r"((r)[1]), "=r"((r)[2]), "=r"((r)[3]) : "r"(addr))

__device__ __forceinline__ void mma_f16(float d[4], const uint32_t a[4],
                                        uint32_t b0, uint32_t b1) {
    asm volatile(
        "mma.sync.aligned.m16n8k16.row.col.f32.f16.f16.f32 "
        "{%0,%1,%2,%3},{%4,%5,%6,%7},{%8,%9},{%0,%1,%2,%3};"
        : "+f"(d[0]), "+f"(d[1]), "+f"(d[2]), "+f"(d[3])
        : "r"(a[0]), "r"(a[1]), "r"(a[2]), "r"(a[3]), "r"(b0), "r"(b1));
}

__device__ __forceinline__ uint32_t pack2(fp16 a, fp16 b) {
    return ((uint32_t)__half_as_ushort(b) << 16) | (uint32_t)__half_as_ushort(a);
}

// ---------------- small kernels ------------------------------------------------
__global__ void zero_counts_kernel() {
    if (threadIdx.x < NEXP) g_cnt[threadIdx.x] = 0;
}

// x -> (hi fp16, lo fp16)
__global__ void cvtx_kernel(const float* __restrict__ in,
                            fp16* __restrict__ oh, fp16* __restrict__ ol, int n4) {
    int i = blockIdx.x * blockDim.x + threadIdx.x;
    if (i >= n4) return;
    float4 v = reinterpret_cast<const float4*>(in)[i];
    fp16 h0 = __float2half(v.x), h1 = __float2half(v.y);
    fp16 h2 = __float2half(v.z), h3 = __float2half(v.w);
    fp16 l0 = __float2half(v.x - __half2float(h0));
    fp16 l1 = __float2half(v.y - __half2float(h1));
    fp16 l2 = __float2half(v.z - __half2float(h2));
    fp16 l3 = __float2half(v.w - __half2float(h3));
    uint2 ph; ph.x = pack2(h0, h1); ph.y = pack2(h2, h3);
    uint2 pl; pl.x = pack2(l0, l1); pl.y = pack2(l2, l3);
    reinterpret_cast<uint2*>(oh)[i] = ph;
    reinterpret_cast<uint2*>(ol)[i] = pl;
}

// transpose+convert: in [z][K][N] fp32 -> oh [z][N][K] fp16
__global__ void cvtT_kernel(const float* __restrict__ in,
                            fp16* __restrict__ oh, int K, int N) {
    __shared__ float tile[32][33];
    size_t z = blockIdx.z;
    in += z * (size_t)K * N;
    oh += z * (size_t)N * K;
    int k0 = blockIdx.y * 32, n0 = blockIdx.x * 32;
    int tx = threadIdx.x, ty = threadIdx.y;
#pragma unroll
    for (int i = 0; i < 32; i += 8)
        tile[ty + i][tx] = in[(size_t)(k0 + ty + i) * N + (n0 + tx)];
    __syncthreads();
#pragma unroll
    for (int i = 0; i < 32; i += 8)
        oh[(size_t)(n0 + ty + i) * K + (k0 + tx)] = __float2half(tile[tx][ty + i]);
}

__global__ void gate_kernel(const float* __restrict__ x, const float* __restrict__ gw) {
    int tok  = (blockIdx.x * blockDim.x + threadIdx.x) >> 5;
    int lane = threadIdx.x & 31;
    if (tok >= TOK) return;
    const float* xr = x + (size_t)tok * DIM;
    float acc[NEXP];
#pragma unroll
    for (int e = 0; e < NEXP; e++) acc[e] = 0.f;
    for (int d = lane; d < DIM; d += 32) {
        float xv = xr[d];
#pragma unroll
        for (int e = 0; e < NEXP; e++) acc[e] = fmaf(xv, gw[e * DIM + d], acc[e]);
    }
#pragma unroll
    for (int e = 0; e < NEXP; e++)
#pragma unroll
        for (int off = 16; off > 0; off >>= 1)
            acc[e] += __shfl_xor_sync(0xffffffffu, acc[e], off);
    if (lane == 0) {
        float mx = acc[0];
#pragma unroll
        for (int e = 1; e < NEXP; e++) mx = fmaxf(mx, acc[e]);
        float p[NEXP], s = 0.f;
#pragma unroll
        for (int e = 0; e < NEXP; e++) { p[e] = expf(acc[e] - mx); s += p[e]; }
        float inv = 1.f / s;
#pragma unroll
        for (int e = 0; e < NEXP; e++) p[e] *= inv;
        int i1 = 0;
#pragma unroll
        for (int e = 1; e < NEXP; e++) if (p[e] > p[i1]) i1 = e;
        int i2 = (i1 == 0) ? 1 : 0;
#pragma unroll
        for (int e = 0; e < NEXP; e++) if (e != i1 && p[e] > p[i2]) i2 = e;
        int pos1 = atomicAdd(&g_cnt[i1], 1);
        g_idx[i1 * TOK + pos1] = tok;  g_wgt[i1 * TOK + pos1] = p[i1];
        g_slot[2 * tok] = i1 * TOK + pos1;
        int pos2 = atomicAdd(&g_cnt[i2], 1);
        g_idx[i2 * TOK + pos2] = tok;  g_wgt[i2 * TOK + pos2] = p[i2];
        g_slot[2 * tok + 1] = i2 * TOK + pos2;
    }
}

// ---------------- GEMM1: fused SwiGLU up-proj (merged routed+shared) -----------
// grid.z in [0,8]: z<8 routed expert z (N=EHID, gathered rows), z==8 shared
// (N=SHID, identity rows). BM=128, BN=64 per B-matrix, BK=32, 256 threads.
#define G1_S_AH   0
#define G1_S_AL   5120
#define G1_S_B1H  10240
#define G1_S_B3H  12800
#define G1_STG    15360
#define G1_SMEM   (2 * G1_STG * 2)   // 61440 B

__global__ void __launch_bounds__(256, 2)
gemm1_kernel() {
    const int K = DIM;
    int z = blockIdx.z;
    bool sh = (z == NEXP);
    int M = sh ? TOK : g_cnt[z];
    int N = sh ? SHID : EHID;
    int rowBlock = blockIdx.y * 128;
    if (rowBlock >= M) return;
    int colBlock = blockIdx.x * 64;
    if (colBlock >= N) return;
    const fp16* B1 = sh ? g_s1h : g_w1h + (size_t)z * EHID * DIM;
    const fp16* B3 = sh ? g_s3h : g_w3h + (size_t)z * EHID * DIM;
    fp16* H        = sh ? g_hsh : g_hh  + (size_t)z * TOK * EHID;

    extern __shared__ __align__(16) fp16 sm1[];
    uint32_t sb0 = smem_u32(sm1);

    int tid = threadIdx.x, lane = tid & 31, warp = tid >> 5;
    int wm = warp >> 2, wn = warp & 3;

    // ---- global load mapping ----
    int ra = tid >> 1, ka = (tid & 1) * 16;
    bool aval = (rowBlock + ra) < M;
    int asrc = aval ? (sh ? rowBlock + ra : g_idx[z * TOK + rowBlock + ra]) : 0;
    const fp16* aph = g_xh + (size_t)asrc * K + ka;
    const fp16* apl = g_xl + (size_t)asrc * K + ka;
    uint32_t adst = (uint32_t)(ra * LDH + ka) * 2;

    int rb = tid >> 2, kb = (tid & 3) * 8;
    const fp16* b1p = B1 + (size_t)(colBlock + rb) * K + kb;
    const fp16* b3p = B3 + (size_t)(colBlock + rb) * K + kb;
    uint32_t bdst = (uint32_t)(rb * LDH + kb) * 2;

    auto load_stage = [&](int s, int k0) {
        uint32_t sb = sb0 + (uint32_t)s * G1_STG * 2;
        cp16(sb + G1_S_AH * 2 + adst,      aph + k0,     aval);
        cp16(sb + G1_S_AH * 2 + adst + 16, aph + k0 + 8, aval);
        cp16(sb + G1_S_AL * 2 + adst,      apl + k0,     aval);
        cp16(sb + G1_S_AL * 2 + adst + 16, apl + k0 + 8, aval);
        cp16(sb + G1_S_B1H * 2 + bdst, b1p + k0, true);
        cp16(sb + G1_S_B3H * 2 + bdst, b3p + k0, true);
    };

    // ---- ldmatrix bases ----
    int lrow = lane & 15, lkA = (lane >> 4) * 8;
    uint32_t aOffH[4], aOffL[4];
#pragma unroll
    for (int mi = 0; mi < 4; mi++) {
        int r = wm * 64 + mi * 16 + lrow;
        aOffH[mi] = (uint32_t)(G1_S_AH + r * LDH + lkA) * 2;
        aOffL[mi] = (uint32_t)(G1_S_AL + r * LDH + lkA) * 2;
    }
    int nloc = (lane & 7) | ((lane & 16) >> 1);
    int lkB  = ((lane >> 3) & 1) * 8;
    uint32_t bRow = (uint32_t)((wn * 16 + nloc) * LDH + lkB) * 2;
    uint32_t b1Off = G1_S_B1H * 2 + bRow;
    uint32_t b3Off = G1_S_B3H * 2 + bRow;

    float acc1[4][2][4], acc3[4][2][4];
#pragma unroll
    for (int i = 0; i < 4; i++)
#pragma unroll
        for (int j = 0; j < 2; j++)
#pragma unroll
            for (int r = 0; r < 4; r++) { acc1[i][j][r] = 0.f; acc3[i][j][r] = 0.f; }

    load_stage(0, 0);
    CP_COMMIT();
    const int nIter = K / 32;
    for (int i = 0; i < nIter; i++) {
        if (i + 1 < nIter) { load_stage((i + 1) & 1, (i + 1) * 32); CP_COMMIT(); CP_WAIT1(); }
        else               { CP_WAIT0(); }
        __syncthreads();
        uint32_t sb = sb0 + (uint32_t)(i & 1) * G1_STG * 2;
#pragma unroll
        for (int ks = 0; ks < 2; ks++) {
            uint32_t ko = (uint32_t)ks * 32;
            uint32_t ah[4][4], al[4][4];
#pragma unroll
            for (int mi = 0; mi < 4; mi++) {
                LDSM4(ah[mi], sb + aOffH[mi] + ko);
                LDSM4(al[mi], sb + aOffL[mi] + ko);
            }
            uint32_t b1[4], b3[4];
            LDSM4(b1, sb + b1Off + ko);
            LDSM4(b3, sb + b3Off + ko);
#pragma unroll
            for (int mi = 0; mi < 4; mi++)
#pragma unroll
                for (int nf = 0; nf < 2; nf++) {
                    mma_f16(acc1[mi][nf], ah[mi], b1[2*nf], b1[2*nf+1]);
                    mma_f16(acc1[mi][nf], al[mi], b1[2*nf], b1[2*nf+1]);
                    mma_f16(acc3[mi][nf], ah[mi], b3[2*nf], b3[2*nf+1]);
                    mma_f16(acc3[mi][nf], al[mi], b3[2*nf], b3[2*nf+1]);
                }
        }
        __syncthreads();
    }

    // ---- epilogue: silu(acc1)*acc3 -> fp16 hi only ----
    int rr = lane >> 2, cc = (lane & 3) * 2;
#pragma unroll
    for (int mi = 0; mi < 4; mi++) {
        int gmb = rowBlock + wm * 64 + mi * 16 + rr;
#pragma unroll
        for (int nf = 0; nf < 2; nf++) {
            int col = colBlock + wn * 16 + nf * 8 + cc;
#pragma unroll
            for (int hf = 0; hf < 2; hf++) {
                int gm = gmb + hf * 8;
                if (gm < M) {
                    float v1a = acc1[mi][nf][hf*2], v1b = acc1[mi][nf][hf*2+1];
                    float v3a = acc3[mi][nf][hf*2], v3b = acc3[mi][nf][hf*2+1];
                    float h0 = v1a / (1.f + expf(-v1a)) * v3a;
                    float h1 = v1b / (1.f + expf(-v1b)) * v3b;
                    *reinterpret_cast<uint32_t*>(H + (size_t)gm * N + col) =
                        pack2(__float2half(h0), __float2half(h1));
                }
            }
        }
    }
}

// ---------------- GEMM2: down-projection (merged, single-term A) ---------------
// grid.z in [0,8]; BM=128, BN=64, BK=32, 256 threads (8 warps: 2m x 4n).
#define G2_S_AH  0
#define G2_S_BH  5120
#define G2_STG   7680
#define G2_SMEM  (2 * G2_STG * 2)    // 30720 B

__global__ void __launch_bounds__(256, 2)
gemm2_kernel(float* __restrict__ out) {
    int z = blockIdx.z;
    bool sh = (z == NEXP);
    int M = sh ? TOK : g_cnt[z];
    int K = sh ? SHID : EHID;
    int rowBlock = blockIdx.y * 128;
    if (rowBlock >= M) return;
    int colBlock = blockIdx.x * 64;
    const fp16* A = sh ? g_hsh : g_hh + (size_t)z * TOK * EHID;
    const fp16* B = sh ? g_s2h : g_w2h + (size_t)z * DIM * EHID;
    float* Y      = sh ? out   : g_yp  + (size_t)z * TOK * DIM;

    extern __shared__ __align__(16) fp16 sm2[];
    uint32_t sb0 = smem_u32(sm2);

    int tid = threadIdx.x, lane = tid & 31, warp = tid >> 5;
    int wm = warp >> 2, wn = warp & 3;

    int ra = tid >> 1, ka = (tid & 1) * 16;
    bool aval = (rowBlock + ra) < M;
    const fp16* aph = A + (size_t)(aval ? rowBlock + ra : 0) * K + ka;
    uint32_t adst = (uint32_t)(ra * LDH + ka) * 2;

    int rb = tid >> 2, kb = (tid & 3) * 8;
    const fp16* bp = B + (size_t)(colBlock + rb) * K + kb;
    uint32_t bdst = (uint32_t)(rb * LDH + kb) * 2;

    auto load_stage = [&](int s, int k0) {
        uint32_t sb = sb0 + (uint32_t)s * G2_STG * 2;
        cp16(sb + G2_S_AH * 2 + adst,      aph + k0,     aval);
        cp16(sb + G2_S_AH * 2 + adst + 16, aph + k0 + 8, aval);
        cp16(sb + G2_S_BH * 2 + bdst, bp + k0, true);
    };

    int lrow = lane & 15, lkA = (lane >> 4) * 8;
    uint32_t aOff[4];
#pragma unroll
    for (int mi = 0; mi < 4; mi++) {
        int r = wm * 64 + mi * 16 + lrow;
        aOff[mi] = (uint32_t)(G2_S_AH + r * LDH + lkA) * 2;
    }
    int nloc = (lane & 7) | ((lane & 16) >> 1);
    int lkB  = ((lane >> 3) & 1) * 8;
    uint32_t bOff = (uint32_t)(G2_S_BH + (wn * 16 + nloc) * LDH + lkB) * 2;

    float acc[4][2][4];
#pragma unroll
    for (int i = 0; i < 4; i++)
#pragma unroll
        for (int j = 0; j < 2; j++)
#pragma unroll
            for (int r = 0; r < 4; r++) acc[i][j][r] = 0.f;

    load_stage(0, 0);
    CP_COMMIT();
    const int nIter = K / 32;
    for (int i = 0; i < nIter; i++) {
        if (i + 1 < nIter) { load_stage((i + 1) & 1, (i + 1) * 32); CP_COMMIT(); CP_WAIT1(); }
        else               { CP_WAIT0(); }
        __syncthreads();
        uint32_t sb = sb0 + (uint32_t)(i & 1) * G2_STG * 2;
#pragma unroll
        for (int ks = 0; ks < 2; ks++) {
            uint32_t ko = (uint32_t)ks * 32;
            uint32_t ah[4][4];
#pragma unroll
            for (int mi = 0; mi < 4; mi++)
                LDSM4(ah[mi], sb + aOff[mi] + ko);
            uint32_t b[4];
            LDSM4(b, sb + bOff + ko);
#pragma unroll
            for (int mi = 0; mi < 4; mi++)
#pragma unroll
                for (int nf = 0; nf < 2; nf++)
                    mma_f16(acc[mi][nf], ah[mi], b[2*nf], b[2*nf+1]);
        }
        __syncthreads();
    }

    int rr = lane >> 2, cc = (lane & 3) * 2;
#pragma unroll
    for (int mi = 0; mi < 4; mi++) {
        int gmb = rowBlock + wm * 64 + mi * 16 + rr;
#pragma unroll
        for (int hf = 0; hf < 2; hf++) {
            int gm = gmb + hf * 8;
            if (gm < M) {
                float w = sh ? 1.0f : g_wgt[z * TOK + gm];
                float* dst = Y + (size_t)gm * DIM;
#pragma unroll
                for (int nf = 0; nf < 2; nf++) {
                    int col = colBlock + wn * 16 + nf * 8 + cc;
                    float2 v;
                    v.x = w * acc[mi][nf][hf*2];
                    v.y = w * acc[mi][nf][hf*2+1];
                    *reinterpret_cast<float2*>(dst + col) = v;
                }
            }
        }
    }
}

// out[t] += yp[slot0(t)] + yp[slot1(t)]
__global__ void combine_kernel(float* __restrict__ out) {
    int t = blockIdx.x;
    int d = threadIdx.x;
    int s0 = g_slot[2 * t], s1 = g_slot[2 * t + 1];
    float4* o = reinterpret_cast<float4*>(out) + (size_t)t * 256 + d;
    const float4 a  = *o;
    const float4 b0 = reinterpret_cast<const float4*>(g_yp)[(size_t)s0 * 256 + d];
    const float4 b1 = reinterpret_cast<const float4*>(g_yp)[(size_t)s1 * 256 + d];
    float4 r;
    r.x = a.x + (b0.x + b1.x);
    r.y = a.y + (b0.y + b1.y);
    r.z = a.z + (b0.z + b1.z);
    r.w = a.w + (b0.w + b1.w);
    *o = r;
}

// ---------------- launcher -----------------------------------------------------
extern "C" void kernel_launch(void* const* d_in, const int* in_sizes, int n_in,
                              void* d_out, int out_size) {
    const float* x   = (const float*)d_in[0];
    const float* gw  = (const float*)d_in[1];
    const float* w1  = (const float*)d_in[2];
    const float* w2  = (const float*)d_in[3];
    const float* w3  = (const float*)d_in[4];
    const float* sw1 = (const float*)d_in[5];
    const float* sw2 = (const float*)d_in[6];
    const float* sw3 = (const float*)d_in[7];
    float* out = (float*)d_out;
    (void)in_sizes; (void)n_in; (void)out_size;

    cudaFuncSetAttribute(gemm1_kernel, cudaFuncAttributeMaxDynamicSharedMemorySize, G1_SMEM);
    cudaFuncSetAttribute(gemm2_kernel, cudaFuncAttributeMaxDynamicSharedMemorySize, G2_SMEM);

    fp16 *xh, *xl, *w1h, *w3h, *w2h, *s1h, *s3h, *s2h;
    cudaGetSymbolAddress((void**)&xh,  g_xh);  cudaGetSymbolAddress((void**)&xl,  g_xl);
    cudaGetSymbolAddress((void**)&w1h, g_w1h); cudaGetSymbolAddress((void**)&w3h, g_w3h);
    cudaGetSymbolAddress((void**)&w2h, g_w2h);
    cudaGetSymbolAddress((void**)&s1h, g_s1h); cudaGetSymbolAddress((void**)&s3h, g_s3h);
    cudaGetSymbolAddress((void**)&s2h, g_s2h);

    zero_counts_kernel<<<1, 32>>>();
    cvtx_kernel<<<(TOK * DIM / 4 + 255) / 256, 256>>>(x, xh, xl, TOK * DIM / 4);
    cvtT_kernel<<<dim3(EHID / 32, DIM / 32, NEXP), dim3(32, 8)>>>(w1, w1h, DIM, EHID);
    cvtT_kernel<<<dim3(EHID / 32, DIM / 32, NEXP), dim3(32, 8)>>>(w3, w3h, DIM, EHID);
    cvtT_kernel<<<dim3(DIM / 32, EHID / 32, NEXP), dim3(32, 8)>>>(w2, w2h, EHID, DIM);
    cvtT_kernel<<<dim3(SHID / 32, DIM / 32, 1),  dim3(32, 8)>>>(sw1, s1h, DIM, SHID);
    cvtT_kernel<<<dim3(SHID / 32, DIM / 32, 1),  dim3(32, 8)>>>(sw3, s3h, DIM, SHID);
    cvtT_kernel<<<dim3(DIM / 32, SHID / 32, 1),  dim3(32, 8)>>>(sw2, s2h, SHID, DIM);
    gate_kernel<<<TOK / 8, 256>>>(x, gw);

    // merged up-proj: z<8 routed experts, z==8 shared expert
    gemm1_kernel<<<dim3(EHID / 64, TOK / 128, NEXP + 1), 256, G1_SMEM>>>();
    // merged down-proj: shared writes d_out, routed writes yp partials
    gemm2_kernel<<<dim3(DIM / 64, TOK / 128, NEXP + 1), 256, G2_SMEM>>>(out);

    combine_kernel<<<TOK, 256>>>(out);
}

// round 8
// speedup vs baseline: 6.4313x; 1.4323x over previous
#include <cuda_runtime.h>
#include <cuda_fp16.h>
#include <math.h>
#include <stdint.h>

#define TOK   4096
#define DIM   1024
#define NEXP  8
#define EHID  2816
#define SHID  1536
#define LDH   40      // smem row stride in fp16 elems (32 data + 8 pad)

typedef __half fp16;

// ---------------- scratch (device globals) ----------------------------------
__device__ fp16  g_xh [(size_t)TOK*DIM];
__device__ fp16  g_w1h[(size_t)NEXP*EHID*DIM];
__device__ fp16  g_w3h[(size_t)NEXP*EHID*DIM];
__device__ fp16  g_w2h[(size_t)NEXP*DIM*EHID];
__device__ fp16  g_s1h[(size_t)SHID*DIM];
__device__ fp16  g_s3h[(size_t)SHID*DIM];
__device__ fp16  g_s2h[(size_t)DIM*SHID];
__device__ fp16  g_hh [(size_t)NEXP*TOK*EHID];   // routed hidden (fp16)
__device__ fp16  g_hsh[(size_t)TOK*SHID];        // shared hidden
__device__ float g_yp [(size_t)NEXP*TOK*DIM];
__device__ int   g_cnt[NEXP];
__device__ int   g_idx[NEXP*TOK];
__device__ float g_wgt[NEXP*TOK];
__device__ int   g_slot[TOK*2];

// ---------------- helpers ----------------------------------------------------
__device__ __forceinline__ uint32_t smem_u32(const void* p) {
    uint32_t a;
    asm("{ .reg .u64 t; cvta.to.shared.u64 t, %1; cvt.u32.u64 %0, t; }"
        : "=r"(a) : "l"(p));
    return a;
}
__device__ __forceinline__ void cp16(uint32_t saddr, const void* g, bool valid) {
    int sz = valid ? 16 : 0;
    asm volatile("cp.async.cg.shared.global [%0], [%1], 16, %2;"
                 :: "r"(saddr), "l"(g), "r"(sz));
}
#define CP_COMMIT() asm volatile("cp.async.commit_group;")
#define CP_WAIT1()  asm volatile("cp.async.wait_group 1;")
#define CP_WAIT0()  asm volatile("cp.async.wait_group 0;")

#define LDSM4(r, addr) \
    asm volatile("ldmatrix.sync.aligned.m8n8.x4.shared.b16 {%0,%1,%2,%3}, [%4];" \
        : "=r"((r)[0]), "=r"((r)[1]), "=r"((r)[2]), "=r"((r)[3]) : "r"(addr))

__device__ __forceinline__ void mma_f16(float d[4], const uint32_t a[4],
                                        uint32_t b0, uint32_t b1) {
    asm volatile(
        "mma.sync.aligned.m16n8k16.row.col.f32.f16.f16.f32 "
        "{%0,%1,%2,%3},{%4,%5,%6,%7},{%8,%9},{%0,%1,%2,%3};"
        : "+f"(d[0]), "+f"(d[1]), "+f"(d[2]), "+f"(d[3])
        : "r"(a[0]), "r"(a[1]), "r"(a[2]), "r"(a[3]), "r"(b0), "r"(b1));
}

__device__ __forceinline__ uint32_t pack2(fp16 a, fp16 b) {
    return ((uint32_t)__half_as_ushort(b) << 16) | (uint32_t)__half_as_ushort(a);
}

// ---------------- small kernels ------------------------------------------------
__global__ void zero_counts_kernel() {
    if (threadIdx.x < NEXP) g_cnt[threadIdx.x] = 0;
}

// x -> fp16
__global__ void cvtx_kernel(const float* __restrict__ in,
                            fp16* __restrict__ oh, int n4) {
    int i = blockIdx.x * blockDim.x + threadIdx.x;
    if (i >= n4) return;
    float4 v = reinterpret_cast<const float4*>(in)[i];
    uint2 ph;
    ph.x = pack2(__float2half(v.x), __float2half(v.y));
    ph.y = pack2(__float2half(v.z), __float2half(v.w));
    reinterpret_cast<uint2*>(oh)[i] = ph;
}

// transpose+convert: in [z][K][N] fp32 -> oh [z][N][K] fp16
__global__ void cvtT_kernel(const float* __restrict__ in,
                            fp16* __restrict__ oh, int K, int N) {
    __shared__ float tile[32][33];
    size_t z = blockIdx.z;
    in += z * (size_t)K * N;
    oh += z * (size_t)N * K;
    int k0 = blockIdx.y * 32, n0 = blockIdx.x * 32;
    int tx = threadIdx.x, ty = threadIdx.y;
#pragma unroll
    for (int i = 0; i < 32; i += 8)
        tile[ty + i][tx] = in[(size_t)(k0 + ty + i) * N + (n0 + tx)];
    __syncthreads();
#pragma unroll
    for (int i = 0; i < 32; i += 8)
        oh[(size_t)(n0 + ty + i) * K + (k0 + tx)] = __float2half(tile[tx][ty + i]);
}

__global__ void gate_kernel(const float* __restrict__ x, const float* __restrict__ gw) {
    int tok  = (blockIdx.x * blockDim.x + threadIdx.x) >> 5;
    int lane = threadIdx.x & 31;
    if (tok >= TOK) return;
    const float* xr = x + (size_t)tok * DIM;
    float acc[NEXP];
#pragma unroll
    for (int e = 0; e < NEXP; e++) acc[e] = 0.f;
    for (int d = lane; d < DIM; d += 32) {
        float xv = xr[d];
#pragma unroll
        for (int e = 0; e < NEXP; e++) acc[e] = fmaf(xv, gw[e * DIM + d], acc[e]);
    }
#pragma unroll
    for (int e = 0; e < NEXP; e++)
#pragma unroll
        for (int off = 16; off > 0; off >>= 1)
            acc[e] += __shfl_xor_sync(0xffffffffu, acc[e], off);
    if (lane == 0) {
        float mx = acc[0];
#pragma unroll
        for (int e = 1; e < NEXP; e++) mx = fmaxf(mx, acc[e]);
        float p[NEXP], s = 0.f;
#pragma unroll
        for (int e = 0; e < NEXP; e++) { p[e] = expf(acc[e] - mx); s += p[e]; }
        float inv = 1.f / s;
#pragma unroll
        for (int e = 0; e < NEXP; e++) p[e] *= inv;
        int i1 = 0;
#pragma unroll
        for (int e = 1; e < NEXP; e++) if (p[e] > p[i1]) i1 = e;
        int i2 = (i1 == 0) ? 1 : 0;
#pragma unroll
        for (int e = 0; e < NEXP; e++) if (e != i1 && p[e] > p[i2]) i2 = e;
        int pos1 = atomicAdd(&g_cnt[i1], 1);
        g_idx[i1 * TOK + pos1] = tok;  g_wgt[i1 * TOK + pos1] = p[i1];
        g_slot[2 * tok] = i1 * TOK + pos1;
        int pos2 = atomicAdd(&g_cnt[i2], 1);
        g_idx[i2 * TOK + pos2] = tok;  g_wgt[i2 * TOK + pos2] = p[i2];
        g_slot[2 * tok + 1] = i2 * TOK + pos2;
    }
}

// ---------------- GEMM1: fused SwiGLU up-proj (merged routed+shared) -----------
// grid.z in [0,8]: z<8 routed expert z (N=EHID, gathered rows), z==8 shared
// (N=SHID, identity rows). BM=128, BN=64 per B-matrix, BK=32, 256 threads.
#define G1_S_AH   0
#define G1_S_B1H  5120
#define G1_S_B3H  7680
#define G1_STG    10240
#define G1_SMEM   (2 * G1_STG * 2)   // 40960 B

__global__ void __launch_bounds__(256, 2)
gemm1_kernel() {
    const int K = DIM;
    int z = blockIdx.z;
    bool sh = (z == NEXP);
    int M = sh ? TOK : g_cnt[z];
    int N = sh ? SHID : EHID;
    int rowBlock = blockIdx.y * 128;
    if (rowBlock >= M) return;
    int colBlock = blockIdx.x * 64;
    if (colBlock >= N) return;
    const fp16* B1 = sh ? g_s1h : g_w1h + (size_t)z * EHID * DIM;
    const fp16* B3 = sh ? g_s3h : g_w3h + (size_t)z * EHID * DIM;
    fp16* H        = sh ? g_hsh : g_hh  + (size_t)z * TOK * EHID;

    extern __shared__ __align__(16) fp16 sm1[];
    uint32_t sb0 = smem_u32(sm1);

    int tid = threadIdx.x, lane = tid & 31, warp = tid >> 5;
    int wm = warp >> 2, wn = warp & 3;

    // ---- global load mapping ----
    int ra = tid >> 1, ka = (tid & 1) * 16;
    bool aval = (rowBlock + ra) < M;
    int asrc = aval ? (sh ? rowBlock + ra : g_idx[z * TOK + rowBlock + ra]) : 0;
    const fp16* aph = g_xh + (size_t)asrc * K + ka;
    uint32_t adst = (uint32_t)(ra * LDH + ka) * 2;

    int rb = tid >> 2, kb = (tid & 3) * 8;
    const fp16* b1p = B1 + (size_t)(colBlock + rb) * K + kb;
    const fp16* b3p = B3 + (size_t)(colBlock + rb) * K + kb;
    uint32_t bdst = (uint32_t)(rb * LDH + kb) * 2;

    auto load_stage = [&](int s, int k0) {
        uint32_t sb = sb0 + (uint32_t)s * G1_STG * 2;
        cp16(sb + G1_S_AH * 2 + adst,      aph + k0,     aval);
        cp16(sb + G1_S_AH * 2 + adst + 16, aph + k0 + 8, aval);
        cp16(sb + G1_S_B1H * 2 + bdst, b1p + k0, true);
        cp16(sb + G1_S_B3H * 2 + bdst, b3p + k0, true);
    };

    // ---- ldmatrix bases ----
    int lrow = lane & 15, lkA = (lane >> 4) * 8;
    uint32_t aOff[4];
#pragma unroll
    for (int mi = 0; mi < 4; mi++) {
        int r = wm * 64 + mi * 16 + lrow;
        aOff[mi] = (uint32_t)(G1_S_AH + r * LDH + lkA) * 2;
    }
    int nloc = (lane & 7) | ((lane & 16) >> 1);
    int lkB  = ((lane >> 3) & 1) * 8;
    uint32_t bRow = (uint32_t)((wn * 16 + nloc) * LDH + lkB) * 2;
    uint32_t b1Off = G1_S_B1H * 2 + bRow;
    uint32_t b3Off = G1_S_B3H * 2 + bRow;

    float acc1[4][2][4], acc3[4][2][4];
#pragma unroll
    for (int i = 0; i < 4; i++)
#pragma unroll
        for (int j = 0; j < 2; j++)
#pragma unroll
            for (int r = 0; r < 4; r++) { acc1[i][j][r] = 0.f; acc3[i][j][r] = 0.f; }

    load_stage(0, 0);
    CP_COMMIT();
    const int nIter = K / 32;
    for (int i = 0; i < nIter; i++) {
        if (i + 1 < nIter) { load_stage((i + 1) & 1, (i + 1) * 32); CP_COMMIT(); CP_WAIT1(); }
        else               { CP_WAIT0(); }
        __syncthreads();
        uint32_t sb = sb0 + (uint32_t)(i & 1) * G1_STG * 2;
#pragma unroll
        for (int ks = 0; ks < 2; ks++) {
            uint32_t ko = (uint32_t)ks * 32;
            uint32_t ah[4][4];
#pragma unroll
            for (int mi = 0; mi < 4; mi++)
                LDSM4(ah[mi], sb + aOff[mi] + ko);
            uint32_t b1[4], b3[4];
            LDSM4(b1, sb + b1Off + ko);
            LDSM4(b3, sb + b3Off + ko);
#pragma unroll
            for (int mi = 0; mi < 4; mi++)
#pragma unroll
                for (int nf = 0; nf < 2; nf++) {
                    mma_f16(acc1[mi][nf], ah[mi], b1[2*nf], b1[2*nf+1]);
                    mma_f16(acc3[mi][nf], ah[mi], b3[2*nf], b3[2*nf+1]);
                }
        }
        __syncthreads();
    }

    // ---- epilogue: silu(acc1)*acc3 -> fp16 ----
    int rr = lane >> 2, cc = (lane & 3) * 2;
#pragma unroll
    for (int mi = 0; mi < 4; mi++) {
        int gmb = rowBlock + wm * 64 + mi * 16 + rr;
#pragma unroll
        for (int nf = 0; nf < 2; nf++) {
            int col = colBlock + wn * 16 + nf * 8 + cc;
#pragma unroll
            for (int hf = 0; hf < 2; hf++) {
                int gm = gmb + hf * 8;
                if (gm < M) {
                    float v1a = acc1[mi][nf][hf*2], v1b = acc1[mi][nf][hf*2+1];
                    float v3a = acc3[mi][nf][hf*2], v3b = acc3[mi][nf][hf*2+1];
                    float h0 = v1a / (1.f + expf(-v1a)) * v3a;
                    float h1 = v1b / (1.f + expf(-v1b)) * v3b;
                    *reinterpret_cast<uint32_t*>(H + (size_t)gm * N + col) =
                        pack2(__float2half(h0), __float2half(h1));
                }
            }
        }
    }
}

// ---------------- GEMM2: down-projection (merged) ------------------------------
// grid.z in [0,8]; BM=128, BN=64, BK=32, 256 threads (8 warps: 2m x 4n).
#define G2_S_AH  0
#define G2_S_BH  5120
#define G2_STG   7680
#define G2_SMEM  (2 * G2_STG * 2)    // 30720 B

__global__ void __launch_bounds__(256, 2)
gemm2_kernel(float* __restrict__ out) {
    int z = blockIdx.z;
    bool sh = (z == NEXP);
    int M = sh ? TOK : g_cnt[z];
    int K = sh ? SHID : EHID;
    int rowBlock = blockIdx.y * 128;
    if (rowBlock >= M) return;
    int colBlock = blockIdx.x * 64;
    const fp16* A = sh ? g_hsh : g_hh + (size_t)z * TOK * EHID;
    const fp16* B = sh ? g_s2h : g_w2h + (size_t)z * DIM * EHID;
    float* Y      = sh ? out   : g_yp  + (size_t)z * TOK * DIM;

    extern __shared__ __align__(16) fp16 sm2[];
    uint32_t sb0 = smem_u32(sm2);

    int tid = threadIdx.x, lane = tid & 31, warp = tid >> 5;
    int wm = warp >> 2, wn = warp & 3;

    int ra = tid >> 1, ka = (tid & 1) * 16;
    bool aval = (rowBlock + ra) < M;
    const fp16* aph = A + (size_t)(aval ? rowBlock + ra : 0) * K + ka;
    uint32_t adst = (uint32_t)(ra * LDH + ka) * 2;

    int rb = tid >> 2, kb = (tid & 3) * 8;
    const fp16* bp = B + (size_t)(colBlock + rb) * K + kb;
    uint32_t bdst = (uint32_t)(rb * LDH + kb) * 2;

    auto load_stage = [&](int s, int k0) {
        uint32_t sb = sb0 + (uint32_t)s * G2_STG * 2;
        cp16(sb + G2_S_AH * 2 + adst,      aph + k0,     aval);
        cp16(sb + G2_S_AH * 2 + adst + 16, aph + k0 + 8, aval);
        cp16(sb + G2_S_BH * 2 + bdst, bp + k0, true);
    };

    int lrow = lane & 15, lkA = (lane >> 4) * 8;
    uint32_t aOff[4];
#pragma unroll
    for (int mi = 0; mi < 4; mi++) {
        int r = wm * 64 + mi * 16 + lrow;
        aOff[mi] = (uint32_t)(G2_S_AH + r * LDH + lkA) * 2;
    }
    int nloc = (lane & 7) | ((lane & 16) >> 1);
    int lkB  = ((lane >> 3) & 1) * 8;
    uint32_t bOff = (uint32_t)(G2_S_BH + (wn * 16 + nloc) * LDH + lkB) * 2;

    float acc[4][2][4];
#pragma unroll
    for (int i = 0; i < 4; i++)
#pragma unroll
        for (int j = 0; j < 2; j++)
#pragma unroll
            for (int r = 0; r < 4; r++) acc[i][j][r] = 0.f;

    load_stage(0, 0);
    CP_COMMIT();
    const int nIter = K / 32;
    for (int i = 0; i < nIter; i++) {
        if (i + 1 < nIter) { load_stage((i + 1) & 1, (i + 1) * 32); CP_COMMIT(); CP_WAIT1(); }
        else               { CP_WAIT0(); }
        __syncthreads();
        uint32_t sb = sb0 + (uint32_t)(i & 1) * G2_STG * 2;
#pragma unroll
        for (int ks = 0; ks < 2; ks++) {
            uint32_t ko = (uint32_t)ks * 32;
            uint32_t ah[4][4];
#pragma unroll
            for (int mi = 0; mi < 4; mi++)
                LDSM4(ah[mi], sb + aOff[mi] + ko);
            uint32_t b[4];
            LDSM4(b, sb + bOff + ko);
#pragma unroll
            for (int mi = 0; mi < 4; mi++)
#pragma unroll
                for (int nf = 0; nf < 2; nf++)
                    mma_f16(acc[mi][nf], ah[mi], b[2*nf], b[2*nf+1]);
        }
        __syncthreads();
    }

    int rr = lane >> 2, cc = (lane & 3) * 2;
#pragma unroll
    for (int mi = 0; mi < 4; mi++) {
        int gmb = rowBlock + wm * 64 + mi * 16 + rr;
#pragma unroll
        for (int hf = 0; hf < 2; hf++) {
            int gm = gmb + hf * 8;
            if (gm < M) {
                float w = sh ? 1.0f : g_wgt[z * TOK + gm];
                float* dst = Y + (size_t)gm * DIM;
#pragma unroll
                for (int nf = 0; nf < 2; nf++) {
                    int col = colBlock + wn * 16 + nf * 8 + cc;
                    float2 v;
                    v.x = w * acc[mi][nf][hf*2];
                    v.y = w * acc[mi][nf][hf*2+1];
                    *reinterpret_cast<float2*>(dst + col) = v;
                }
            }
        }
    }
}

// out[t] += yp[slot0(t)] + yp[slot1(t)]
__global__ void combine_kernel(float* __restrict__ out) {
    int t = blockIdx.x;
    int d = threadIdx.x;
    int s0 = g_slot[2 * t], s1 = g_slot[2 * t + 1];
    float4* o = reinterpret_cast<float4*>(out) + (size_t)t * 256 + d;
    const float4 a  = *o;
    const float4 b0 = reinterpret_cast<const float4*>(g_yp)[(size_t)s0 * 256 + d];
    const float4 b1 = reinterpret_cast<const float4*>(g_yp)[(size_t)s1 * 256 + d];
    float4 r;
    r.x = a.x + (b0.x + b1.x);
    r.y = a.y + (b0.y + b1.y);
    r.z = a.z + (b0.z + b1.z);
    r.w = a.w + (b0.w + b1.w);
    *o = r;
}

// ---------------- launcher -----------------------------------------------------
extern "C" void kernel_launch(void* const* d_in, const int* in_sizes, int n_in,
                              void* d_out, int out_size) {
    const float* x   = (const float*)d_in[0];
    const float* gw  = (const float*)d_in[1];
    const float* w1  = (const float*)d_in[2];
    const float* w2  = (const float*)d_in[3];
    const float* w3  = (const float*)d_in[4];
    const float* sw1 = (const float*)d_in[5];
    const float* sw2 = (const float*)d_in[6];
    const float* sw3 = (const float*)d_in[7];
    float* out = (float*)d_out;
    (void)in_sizes; (void)n_in; (void)out_size;

    cudaFuncSetAttribute(gemm1_kernel, cudaFuncAttributeMaxDynamicSharedMemorySize, G1_SMEM);
    cudaFuncSetAttribute(gemm2_kernel, cudaFuncAttributeMaxDynamicSharedMemorySize, G2_SMEM);

    fp16 *xh, *w1h, *w3h, *w2h, *s1h, *s3h, *s2h;
    cudaGetSymbolAddress((void**)&xh,  g_xh);
    cudaGetSymbolAddress((void**)&w1h, g_w1h); cudaGetSymbolAddress((void**)&w3h, g_w3h);
    cudaGetSymbolAddress((void**)&w2h, g_w2h);
    cudaGetSymbolAddress((void**)&s1h, g_s1h); cudaGetSymbolAddress((void**)&s3h, g_s3h);
    cudaGetSymbolAddress((void**)&s2h, g_s2h);

    zero_counts_kernel<<<1, 32>>>();
    cvtx_kernel<<<(TOK * DIM / 4 + 255) / 256, 256>>>(x, xh, TOK * DIM / 4);
    cvtT_kernel<<<dim3(EHID / 32, DIM / 32, NEXP), dim3(32, 8)>>>(w1, w1h, DIM, EHID);
    cvtT_kernel<<<dim3(EHID / 32, DIM / 32, NEXP), dim3(32, 8)>>>(w3, w3h, DIM, EHID);
    cvtT_kernel<<<dim3(DIM / 32, EHID / 32, NEXP), dim3(32, 8)>>>(w2, w2h, EHID, DIM);
    cvtT_kernel<<<dim3(SHID / 32, DIM / 32, 1),  dim3(32, 8)>>>(sw1, s1h, DIM, SHID);
    cvtT_kernel<<<dim3(SHID / 32, DIM / 32, 1),  dim3(32, 8)>>>(sw3, s3h, DIM, SHID);
    cvtT_kernel<<<dim3(DIM / 32, SHID / 32, 1),  dim3(32, 8)>>>(sw2, s2h, SHID, DIM);
    gate_kernel<<<TOK / 8, 256>>>(x, gw);

    // merged up-proj: z<8 routed experts, z==8 shared expert
    gemm1_kernel<<<dim3(EHID / 64, TOK / 128, NEXP + 1), 256, G1_SMEM>>>();
    // merged down-proj: shared writes d_out, routed writes yp partials
    gemm2_kernel<<<dim3(DIM / 64, TOK / 128, NEXP + 1), 256, G2_SMEM>>>(out);

    combine_kernel<<<TOK, 256>>>(out);
}

// round 9
// speedup vs baseline: 6.5407x; 1.0170x over previous
#include <cuda_runtime.h>
#include <cuda_fp16.h>
#include <math.h>
#include <stdint.h>

#define TOK   4096
#define DIM   1024
#define NEXP  8
#define EHID  2816
#define SHID  1536
#define LDH   40      // smem row stride in fp16 elems (32 data + 8 pad)

typedef __half fp16;

// ---------------- scratch (device globals) ----------------------------------
__device__ fp16  g_xh [(size_t)TOK*DIM];
__device__ fp16  g_w1h[(size_t)NEXP*EHID*DIM];
__device__ fp16  g_w3h[(size_t)NEXP*EHID*DIM];
__device__ fp16  g_w2h[(size_t)NEXP*DIM*EHID];
__device__ fp16  g_s1h[(size_t)SHID*DIM];
__device__ fp16  g_s3h[(size_t)SHID*DIM];
__device__ fp16  g_s2h[(size_t)DIM*SHID];
__device__ fp16  g_hh [(size_t)NEXP*TOK*EHID];   // routed hidden (fp16)
__device__ fp16  g_hsh[(size_t)TOK*SHID];        // shared hidden
__device__ float g_yp [(size_t)NEXP*TOK*DIM];
__device__ int   g_cnt[NEXP];
__device__ int   g_idx[NEXP*TOK];
__device__ float g_wgt[NEXP*TOK];
__device__ int   g_slot[TOK*2];

// ---------------- helpers ----------------------------------------------------
__device__ __forceinline__ uint32_t smem_u32(const void* p) {
    uint32_t a;
    asm("{ .reg .u64 t; cvta.to.shared.u64 t, %1; cvt.u32.u64 %0, t; }"
        : "=r"(a) : "l"(p));
    return a;
}
__device__ __forceinline__ void cp16(uint32_t saddr, const void* g, bool valid) {
    int sz = valid ? 16 : 0;
    asm volatile("cp.async.cg.shared.global [%0], [%1], 16, %2;"
                 :: "r"(saddr), "l"(g), "r"(sz));
}
#define CP_COMMIT() asm volatile("cp.async.commit_group;")
#define CP_WAIT1()  asm volatile("cp.async.wait_group 1;")
#define CP_WAIT0()  asm volatile("cp.async.wait_group 0;")

#define LDSM4(r, addr) \
    asm volatile("ldmatrix.sync.aligned.m8n8.x4.shared.b16 {%0,%1,%2,%3}, [%4];" \
        : "=r"((r)[0]), "=r"((r)[1]), "=r"((r)[2]), "=r"((r)[3]) : "r"(addr))

__device__ __forceinline__ void mma_f16(float d[4], const uint32_t a[4],
                                        uint32_t b0, uint32_t b1) {
    asm volatile(
        "mma.sync.aligned.m16n8k16.row.col.f32.f16.f16.f32 "
        "{%0,%1,%2,%3},{%4,%5,%6,%7},{%8,%9},{%0,%1,%2,%3};"
        : "+f"(d[0]), "+f"(d[1]), "+f"(d[2]), "+f"(d[3])
        : "r"(a[0]), "r"(a[1]), "r"(a[2]), "r"(a[3]), "r"(b0), "r"(b1));
}

__device__ __forceinline__ uint32_t pack2(fp16 a, fp16 b) {
    return ((uint32_t)__half_as_ushort(b) << 16) | (uint32_t)__half_as_ushort(a);
}

// ---------------- small kernels ------------------------------------------------
__global__ void zero_counts_kernel() {
    if (threadIdx.x < NEXP) g_cnt[threadIdx.x] = 0;
}

// x -> fp16
__global__ void cvtx_kernel(const float* __restrict__ in,
                            fp16* __restrict__ oh, int n4) {
    int i = blockIdx.x * blockDim.x + threadIdx.x;
    if (i >= n4) return;
    float4 v = reinterpret_cast<const float4*>(in)[i];
    uint2 ph;
    ph.x = pack2(__float2half(v.x), __float2half(v.y));
    ph.y = pack2(__float2half(v.z), __float2half(v.w));
    reinterpret_cast<uint2*>(oh)[i] = ph;
}

// ---------------- merged weight transpose+convert ------------------------------
// One 32x32 tile per block, 256 threads. All 6 weight tensors in one grid.
// Tile counts: w1/w3: 8*(32k*88n)=22528 each; w2: 8*(88k*32n)=22528;
// sw1/sw3: 32*48=1536 each; sw2: 48*32=1536. Total 72192.
#define T_W1   22528
#define T_W3   45056
#define T_W2   67584
#define T_S1   69120
#define T_S3   70656
#define T_ALL  72192

__device__ __forceinline__ void cvt_tile(const float* __restrict__ in,
                                         fp16* __restrict__ out,
                                         int K, int N, int kt, int nt) {
    __shared__ float tile[32][33];
    int k0 = kt * 32, n0 = nt * 32;
    int idx = threadIdx.x;
    int tx = idx & 31, ty = idx >> 5;          // load: 8 rows/pass
#pragma unroll
    for (int j = 0; j < 4; j++)
        tile[ty + 8 * j][tx] = in[(size_t)(k0 + ty + 8 * j) * N + (n0 + tx)];
    __syncthreads();
    int nl = idx >> 3, kq = (idx & 7) * 4;     // write: 4 halves = 8B per thread
    float v0 = tile[kq + 0][nl], v1 = tile[kq + 1][nl];
    float v2 = tile[kq + 2][nl], v3 = tile[kq + 3][nl];
    uint2 o;
    o.x = pack2(__float2half(v0), __float2half(v1));
    o.y = pack2(__float2half(v2), __float2half(v3));
    *reinterpret_cast<uint2*>(out + (size_t)(n0 + nl) * K + k0 + kq) = o;
}

__global__ void __launch_bounds__(256)
cvt_all_kernel(const float* __restrict__ w1, const float* __restrict__ w3,
               const float* __restrict__ w2, const float* __restrict__ sw1,
               const float* __restrict__ sw3, const float* __restrict__ sw2) {
    int t = blockIdx.x;
    if (t < T_W1) {
        int z = t / (32 * 88), r = t % (32 * 88);
        cvt_tile(w1 + (size_t)z * DIM * EHID, g_w1h + (size_t)z * EHID * DIM,
                 DIM, EHID, r % 32, r / 32);
    } else if (t < T_W3) {
        t -= T_W1;
        int z = t / (32 * 88), r = t % (32 * 88);
        cvt_tile(w3 + (size_t)z * DIM * EHID, g_w3h + (size_t)z * EHID * DIM,
                 DIM, EHID, r % 32, r / 32);
    } else if (t < T_W2) {
        t -= T_W3;
        int z = t / (88 * 32), r = t % (88 * 32);
        cvt_tile(w2 + (size_t)z * EHID * DIM, g_w2h + (size_t)z * DIM * EHID,
                 EHID, DIM, r % 88, r / 88);
    } else if (t < T_S1) {
        t -= T_W2;
        cvt_tile(sw1, g_s1h, DIM, SHID, t % 32, t / 32);
    } else if (t < T_S3) {
        t -= T_S1;
        cvt_tile(sw3, g_s3h, DIM, SHID, t % 32, t / 32);
    } else {
        t -= T_S3;
        cvt_tile(sw2, g_s2h, SHID, DIM, t % 48, t / 48);
    }
}

__global__ void gate_kernel(const float* __restrict__ x, const float* __restrict__ gw) {
    int tok  = (blockIdx.x * blockDim.x + threadIdx.x) >> 5;
    int lane = threadIdx.x & 31;
    if (tok >= TOK) return;
    const float* xr = x + (size_t)tok * DIM;
    float acc[NEXP];
#pragma unroll
    for (int e = 0; e < NEXP; e++) acc[e] = 0.f;
    for (int d = lane; d < DIM; d += 32) {
        float xv = xr[d];
#pragma unroll
        for (int e = 0; e < NEXP; e++) acc[e] = fmaf(xv, gw[e * DIM + d], acc[e]);
    }
#pragma unroll
    for (int e = 0; e < NEXP; e++)
#pragma unroll
        for (int off = 16; off > 0; off >>= 1)
            acc[e] += __shfl_xor_sync(0xffffffffu, acc[e], off);
    if (lane == 0) {
        float mx = acc[0];
#pragma unroll
        for (int e = 1; e < NEXP; e++) mx = fmaxf(mx, acc[e]);
        float p[NEXP], s = 0.f;
#pragma unroll
        for (int e = 0; e < NEXP; e++) { p[e] = expf(acc[e] - mx); s += p[e]; }
        float inv = 1.f / s;
#pragma unroll
        for (int e = 0; e < NEXP; e++) p[e] *= inv;
        int i1 = 0;
#pragma unroll
        for (int e = 1; e < NEXP; e++) if (p[e] > p[i1]) i1 = e;
        int i2 = (i1 == 0) ? 1 : 0;
#pragma unroll
        for (int e = 0; e < NEXP; e++) if (e != i1 && p[e] > p[i2]) i2 = e;
        int pos1 = atomicAdd(&g_cnt[i1], 1);
        g_idx[i1 * TOK + pos1] = tok;  g_wgt[i1 * TOK + pos1] = p[i1];
        g_slot[2 * tok] = i1 * TOK + pos1;
        int pos2 = atomicAdd(&g_cnt[i2], 1);
        g_idx[i2 * TOK + pos2] = tok;  g_wgt[i2 * TOK + pos2] = p[i2];
        g_slot[2 * tok + 1] = i2 * TOK + pos2;
    }
}

// ---------------- GEMM1: fused SwiGLU up-proj (merged routed+shared) -----------
// grid.z in [0,8]: z<8 routed expert z (N=EHID, gathered rows), z==8 shared
// (N=SHID, identity rows). BM=128, BN=64 per B-matrix, BK=32, 256 threads.
#define G1_S_AH   0
#define G1_S_B1H  5120
#define G1_S_B3H  7680
#define G1_STG    10240
#define G1_SMEM   (2 * G1_STG * 2)   // 40960 B

__global__ void __launch_bounds__(256, 2)
gemm1_kernel() {
    const int K = DIM;
    int z = blockIdx.z;
    bool sh = (z == NEXP);
    int M = sh ? TOK : g_cnt[z];
    int N = sh ? SHID : EHID;
    int rowBlock = blockIdx.y * 128;
    if (rowBlock >= M) return;
    int colBlock = blockIdx.x * 64;
    if (colBlock >= N) return;
    const fp16* B1 = sh ? g_s1h : g_w1h + (size_t)z * EHID * DIM;
    const fp16* B3 = sh ? g_s3h : g_w3h + (size_t)z * EHID * DIM;
    fp16* H        = sh ? g_hsh : g_hh  + (size_t)z * TOK * EHID;

    extern __shared__ __align__(16) fp16 sm1[];
    uint32_t sb0 = smem_u32(sm1);

    int tid = threadIdx.x, lane = tid & 31, warp = tid >> 5;
    int wm = warp >> 2, wn = warp & 3;

    int ra = tid >> 1, ka = (tid & 1) * 16;
    bool aval = (rowBlock + ra) < M;
    int asrc = aval ? (sh ? rowBlock + ra : g_idx[z * TOK + rowBlock + ra]) : 0;
    const fp16* aph = g_xh + (size_t)asrc * K + ka;
    uint32_t adst = (uint32_t)(ra * LDH + ka) * 2;

    int rb = tid >> 2, kb = (tid & 3) * 8;
    const fp16* b1p = B1 + (size_t)(colBlock + rb) * K + kb;
    const fp16* b3p = B3 + (size_t)(colBlock + rb) * K + kb;
    uint32_t bdst = (uint32_t)(rb * LDH + kb) * 2;

    auto load_stage = [&](int s, int k0) {
        uint32_t sb = sb0 + (uint32_t)s * G1_STG * 2;
        cp16(sb + G1_S_AH * 2 + adst,      aph + k0,     aval);
        cp16(sb + G1_S_AH * 2 + adst + 16, aph + k0 + 8, aval);
        cp16(sb + G1_S_B1H * 2 + bdst, b1p + k0, true);
        cp16(sb + G1_S_B3H * 2 + bdst, b3p + k0, true);
    };

    int lrow = lane & 15, lkA = (lane >> 4) * 8;
    uint32_t aOff[4];
#pragma unroll
    for (int mi = 0; mi < 4; mi++) {
        int r = wm * 64 + mi * 16 + lrow;
        aOff[mi] = (uint32_t)(G1_S_AH + r * LDH + lkA) * 2;
    }
    int nloc = (lane & 7) | ((lane & 16) >> 1);
    int lkB  = ((lane >> 3) & 1) * 8;
    uint32_t bRow = (uint32_t)((wn * 16 + nloc) * LDH + lkB) * 2;
    uint32_t b1Off = G1_S_B1H * 2 + bRow;
    uint32_t b3Off = G1_S_B3H * 2 + bRow;

    float acc1[4][2][4], acc3[4][2][4];
#pragma unroll
    for (int i = 0; i < 4; i++)
#pragma unroll
        for (int j = 0; j < 2; j++)
#pragma unroll
            for (int r = 0; r < 4; r++) { acc1[i][j][r] = 0.f; acc3[i][j][r] = 0.f; }

    load_stage(0, 0);
    CP_COMMIT();
    const int nIter = K / 32;
    for (int i = 0; i < nIter; i++) {
        if (i + 1 < nIter) { load_stage((i + 1) & 1, (i + 1) * 32); CP_COMMIT(); CP_WAIT1(); }
        else               { CP_WAIT0(); }
        __syncthreads();
        uint32_t sb = sb0 + (uint32_t)(i & 1) * G1_STG * 2;
#pragma unroll
        for (int ks = 0; ks < 2; ks++) {
            uint32_t ko = (uint32_t)ks * 32;
            uint32_t ah[4][4];
#pragma unroll
            for (int mi = 0; mi < 4; mi++)
                LDSM4(ah[mi], sb + aOff[mi] + ko);
            uint32_t b1[4], b3[4];
            LDSM4(b1, sb + b1Off + ko);
            LDSM4(b3, sb + b3Off + ko);
#pragma unroll
            for (int mi = 0; mi < 4; mi++)
#pragma unroll
                for (int nf = 0; nf < 2; nf++) {
                    mma_f16(acc1[mi][nf], ah[mi], b1[2*nf], b1[2*nf+1]);
                    mma_f16(acc3[mi][nf], ah[mi], b3[2*nf], b3[2*nf+1]);
                }
        }
        __syncthreads();
    }

    int rr = lane >> 2, cc = (lane & 3) * 2;
#pragma unroll
    for (int mi = 0; mi < 4; mi++) {
        int gmb = rowBlock + wm * 64 + mi * 16 + rr;
#pragma unroll
        for (int nf = 0; nf < 2; nf++) {
            int col = colBlock + wn * 16 + nf * 8 + cc;
#pragma unroll
            for (int hf = 0; hf < 2; hf++) {
                int gm = gmb + hf * 8;
                if (gm < M) {
                    float v1a = acc1[mi][nf][hf*2], v1b = acc1[mi][nf][hf*2+1];
                    float v3a = acc3[mi][nf][hf*2], v3b = acc3[mi][nf][hf*2+1];
                    float h0 = v1a / (1.f + expf(-v1a)) * v3a;
                    float h1 = v1b / (1.f + expf(-v1b)) * v3b;
                    *reinterpret_cast<uint32_t*>(H + (size_t)gm * N + col) =
                        pack2(__float2half(h0), __float2half(h1));
                }
            }
        }
    }
}

// ---------------- GEMM2: down-projection (merged) ------------------------------
#define G2_S_AH  0
#define G2_S_BH  5120
#define G2_STG   7680
#define G2_SMEM  (2 * G2_STG * 2)    // 30720 B

__global__ void __launch_bounds__(256, 2)
gemm2_kernel(float* __restrict__ out) {
    int z = blockIdx.z;
    bool sh = (z == NEXP);
    int M = sh ? TOK : g_cnt[z];
    int K = sh ? SHID : EHID;
    int rowBlock = blockIdx.y * 128;
    if (rowBlock >= M) return;
    int colBlock = blockIdx.x * 64;
    const fp16* A = sh ? g_hsh : g_hh + (size_t)z * TOK * EHID;
    const fp16* B = sh ? g_s2h : g_w2h + (size_t)z * DIM * EHID;
    float* Y      = sh ? out   : g_yp  + (size_t)z * TOK * DIM;

    extern __shared__ __align__(16) fp16 sm2[];
    uint32_t sb0 = smem_u32(sm2);

    int tid = threadIdx.x, lane = tid & 31, warp = tid >> 5;
    int wm = warp >> 2, wn = warp & 3;

    int ra = tid >> 1, ka = (tid & 1) * 16;
    bool aval = (rowBlock + ra) < M;
    const fp16* aph = A + (size_t)(aval ? rowBlock + ra : 0) * K + ka;
    uint32_t adst = (uint32_t)(ra * LDH + ka) * 2;

    int rb = tid >> 2, kb = (tid & 3) * 8;
    const fp16* bp = B + (size_t)(colBlock + rb) * K + kb;
    uint32_t bdst = (uint32_t)(rb * LDH + kb) * 2;

    auto load_stage = [&](int s, int k0) {
        uint32_t sb = sb0 + (uint32_t)s * G2_STG * 2;
        cp16(sb + G2_S_AH * 2 + adst,      aph + k0,     aval);
        cp16(sb + G2_S_AH * 2 + adst + 16, aph + k0 + 8, aval);
        cp16(sb + G2_S_BH * 2 + bdst, bp + k0, true);
    };

    int lrow = lane & 15, lkA = (lane >> 4) * 8;
    uint32_t aOff[4];
#pragma unroll
    for (int mi = 0; mi < 4; mi++) {
        int r = wm * 64 + mi * 16 + lrow;
        aOff[mi] = (uint32_t)(G2_S_AH + r * LDH + lkA) * 2;
    }
    int nloc = (lane & 7) | ((lane & 16) >> 1);
    int lkB  = ((lane >> 3) & 1) * 8;
    uint32_t bOff = (uint32_t)(G2_S_BH + (wn * 16 + nloc) * LDH + lkB) * 2;

    float acc[4][2][4];
#pragma unroll
    for (int i = 0; i < 4; i++)
#pragma unroll
        for (int j = 0; j < 2; j++)
#pragma unroll
            for (int r = 0; r < 4; r++) acc[i][j][r] = 0.f;

    load_stage(0, 0);
    CP_COMMIT();
    const int nIter = K / 32;
    for (int i = 0; i < nIter; i++) {
        if (i + 1 < nIter) { load_stage((i + 1) & 1, (i + 1) * 32); CP_COMMIT(); CP_WAIT1(); }
        else               { CP_WAIT0(); }
        __syncthreads();
        uint32_t sb = sb0 + (uint32_t)(i & 1) * G2_STG * 2;
#pragma unroll
        for (int ks = 0; ks < 2; ks++) {
            uint32_t ko = (uint32_t)ks * 32;
            uint32_t ah[4][4];
#pragma unroll
            for (int mi = 0; mi < 4; mi++)
                LDSM4(ah[mi], sb + aOff[mi] + ko);
            uint32_t b[4];
            LDSM4(b, sb + bOff + ko);
#pragma unroll
            for (int mi = 0; mi < 4; mi++)
#pragma unroll
                for (int nf = 0; nf < 2; nf++)
                    mma_f16(acc[mi][nf], ah[mi], b[2*nf], b[2*nf+1]);
        }
        __syncthreads();
    }

    int rr = lane >> 2, cc = (lane & 3) * 2;
#pragma unroll
    for (int mi = 0; mi < 4; mi++) {
        int gmb = rowBlock + wm * 64 + mi * 16 + rr;
#pragma unroll
        for (int hf = 0; hf < 2; hf++) {
            int gm = gmb + hf * 8;
            if (gm < M) {
                float w = sh ? 1.0f : g_wgt[z * TOK + gm];
                float* dst = Y + (size_t)gm * DIM;
#pragma unroll
                for (int nf = 0; nf < 2; nf++) {
                    int col = colBlock + wn * 16 + nf * 8 + cc;
                    float2 v;
                    v.x = w * acc[mi][nf][hf*2];
                    v.y = w * acc[mi][nf][hf*2+1];
                    *reinterpret_cast<float2*>(dst + col) = v;
                }
            }
        }
    }
}

// out[t] += yp[slot0(t)] + yp[slot1(t)]
__global__ void combine_kernel(float* __restrict__ out) {
    int t = blockIdx.x;
    int d = threadIdx.x;
    int s0 = g_slot[2 * t], s1 = g_slot[2 * t + 1];
    float4* o = reinterpret_cast<float4*>(out) + (size_t)t * 256 + d;
    const float4 a  = *o;
    const float4 b0 = reinterpret_cast<const float4*>(g_yp)[(size_t)s0 * 256 + d];
    const float4 b1 = reinterpret_cast<const float4*>(g_yp)[(size_t)s1 * 256 + d];
    float4 r;
    r.x = a.x + (b0.x + b1.x);
    r.y = a.y + (b0.y + b1.y);
    r.z = a.z + (b0.z + b1.z);
    r.w = a.w + (b0.w + b1.w);
    *o = r;
}

// ---------------- launcher -----------------------------------------------------
extern "C" void kernel_launch(void* const* d_in, const int* in_sizes, int n_in,
                              void* d_out, int out_size) {
    const float* x   = (const float*)d_in[0];
    const float* gw  = (const float*)d_in[1];
    const float* w1  = (const float*)d_in[2];
    const float* w2  = (const float*)d_in[3];
    const float* w3  = (const float*)d_in[4];
    const float* sw1 = (const float*)d_in[5];
    const float* sw2 = (const float*)d_in[6];
    const float* sw3 = (const float*)d_in[7];
    float* out = (float*)d_out;
    (void)in_sizes; (void)n_in; (void)out_size;

    cudaFuncSetAttribute(gemm1_kernel, cudaFuncAttributeMaxDynamicSharedMemorySize, G1_SMEM);
    cudaFuncSetAttribute(gemm2_kernel, cudaFuncAttributeMaxDynamicSharedMemorySize, G2_SMEM);

    fp16* xh;
    cudaGetSymbolAddress((void**)&xh, g_xh);

    zero_counts_kernel<<<1, 32>>>();
    cvtx_kernel<<<(TOK * DIM / 4 + 255) / 256, 256>>>(x, xh, TOK * DIM / 4);
    cvt_all_kernel<<<T_ALL, 256>>>(w1, w3, w2, sw1, sw3, sw2);
    gate_kernel<<<TOK / 8, 256>>>(x, gw);

    // merged up-proj: z<8 routed experts, z==8 shared expert
    gemm1_kernel<<<dim3(EHID / 64, TOK / 128, NEXP + 1), 256, G1_SMEM>>>();
    // merged down-proj: shared writes d_out, routed writes yp partials
    gemm2_kernel<<<dim3(DIM / 64, TOK / 128, NEXP + 1), 256, G2_SMEM>>>(out);

    combine_kernel<<<TOK, 256>>>(out);
}

// round 10
// speedup vs baseline: 6.5747x; 1.0052x over previous
#include <cuda_runtime.h>
#include <cuda_fp16.h>
#include <math.h>
#include <stdint.h>

#define TOK   4096
#define DIM   1024
#define NEXP  8
#define EHID  2816
#define SHID  1536
#define LDH   40      // smem row stride in fp16 elems (32 data + 8 pad)

typedef __half fp16;

// ---------------- scratch (device globals) ----------------------------------
__device__ fp16  g_xh [(size_t)TOK*DIM];
__device__ fp16  g_w1h[(size_t)NEXP*EHID*DIM];
__device__ fp16  g_w3h[(size_t)NEXP*EHID*DIM];
__device__ fp16  g_w2h[(size_t)NEXP*DIM*EHID];
__device__ fp16  g_s1h[(size_t)SHID*DIM];
__device__ fp16  g_s3h[(size_t)SHID*DIM];
__device__ fp16  g_s2h[(size_t)DIM*SHID];
__device__ fp16  g_hh [(size_t)NEXP*TOK*EHID];   // routed hidden (fp16)
__device__ fp16  g_hsh[(size_t)TOK*SHID];        // shared hidden
__device__ float g_yp [(size_t)NEXP*TOK*DIM];
__device__ int   g_cnt[NEXP];
__device__ int   g_idx[NEXP*TOK];
__device__ float g_wgt[NEXP*TOK];
__device__ int   g_slot[TOK*2];

// ---------------- helpers ----------------------------------------------------
__device__ __forceinline__ uint32_t smem_u32(const void* p) {
    uint32_t a;
    asm("{ .reg .u64 t; cvta.to.shared.u64 t, %1; cvt.u32.u64 %0, t; }"
        : "=r"(a) : "l"(p));
    return a;
}
__device__ __forceinline__ void cp16(uint32_t saddr, const void* g, bool valid) {
    int sz = valid ? 16 : 0;
    asm volatile("cp.async.cg.shared.global [%0], [%1], 16, %2;"
                 :: "r"(saddr), "l"(g), "r"(sz));
}
#define CP_COMMIT() asm volatile("cp.async.commit_group;")
#define CP_WAIT1()  asm volatile("cp.async.wait_group 1;")
#define CP_WAIT0()  asm volatile("cp.async.wait_group 0;")

#define LDSM4(r, addr) \
    asm volatile("ldmatrix.sync.aligned.m8n8.x4.shared.b16 {%0,%1,%2,%3}, [%4];" \
        : "=r"((r)[0]), "=r"((r)[1]), "=r"((r)[2]), "=r"((r)[3]) : "r"(addr))

__device__ __forceinline__ void mma_f16(float d[4], const uint32_t a[4],
                                        uint32_t b0, uint32_t b1) {
    asm volatile(
        "mma.sync.aligned.m16n8k16.row.col.f32.f16.f16.f32 "
        "{%0,%1,%2,%3},{%4,%5,%6,%7},{%8,%9},{%0,%1,%2,%3};"
        : "+f"(d[0]), "+f"(d[1]), "+f"(d[2]), "+f"(d[3])
        : "r"(a[0]), "r"(a[1]), "r"(a[2]), "r"(a[3]), "r"(b0), "r"(b1));
}

__device__ __forceinline__ uint32_t pack2(fp16 a, fp16 b) {
    return ((uint32_t)__half_as_ushort(b) << 16) | (uint32_t)__half_as_ushort(a);
}

// ---------------- merged weight transpose+convert (also zeroes g_cnt) ----------
// One 32x32 tile per block, 256 threads. All 6 weight tensors in one grid.
#define T_W1   22528
#define T_W3   45056
#define T_W2   67584
#define T_S1   69120
#define T_S3   70656
#define T_ALL  72192

__device__ __forceinline__ void cvt_tile(const float* __restrict__ in,
                                         fp16* __restrict__ out,
                                         int K, int N, int kt, int nt) {
    __shared__ float tile[32][33];
    int k0 = kt * 32, n0 = nt * 32;
    int idx = threadIdx.x;
    int tx = idx & 31, ty = idx >> 5;          // load: 8 rows/pass
#pragma unroll
    for (int j = 0; j < 4; j++)
        tile[ty + 8 * j][tx] = in[(size_t)(k0 + ty + 8 * j) * N + (n0 + tx)];
    __syncthreads();
    int nl = idx >> 3, kq = (idx & 7) * 4;     // write: 4 halves = 8B per thread
    float v0 = tile[kq + 0][nl], v1 = tile[kq + 1][nl];
    float v2 = tile[kq + 2][nl], v3 = tile[kq + 3][nl];
    uint2 o;
    o.x = pack2(__float2half(v0), __float2half(v1));
    o.y = pack2(__float2half(v2), __float2half(v3));
    *reinterpret_cast<uint2*>(out + (size_t)(n0 + nl) * K + k0 + kq) = o;
}

__global__ void __launch_bounds__(256)
cvt_all_kernel(const float* __restrict__ w1, const float* __restrict__ w3,
               const float* __restrict__ w2, const float* __restrict__ sw1,
               const float* __restrict__ sw3, const float* __restrict__ sw2) {
    int t = blockIdx.x;
    if (t == 0 && threadIdx.x < NEXP) g_cnt[threadIdx.x] = 0;
    if (t < T_W1) {
        int z = t / (32 * 88), r = t % (32 * 88);
        cvt_tile(w1 + (size_t)z * DIM * EHID, g_w1h + (size_t)z * EHID * DIM,
                 DIM, EHID, r % 32, r / 32);
    } else if (t < T_W3) {
        t -= T_W1;
        int z = t / (32 * 88), r = t % (32 * 88);
        cvt_tile(w3 + (size_t)z * DIM * EHID, g_w3h + (size_t)z * EHID * DIM,
                 DIM, EHID, r % 32, r / 32);
    } else if (t < T_W2) {
        t -= T_W3;
        int z = t / (88 * 32), r = t % (88 * 32);
        cvt_tile(w2 + (size_t)z * EHID * DIM, g_w2h + (size_t)z * DIM * EHID,
                 EHID, DIM, r % 88, r / 88);
    } else if (t < T_S1) {
        t -= T_W2;
        cvt_tile(sw1, g_s1h, DIM, SHID, t % 32, t / 32);
    } else if (t < T_S3) {
        t -= T_S1;
        cvt_tile(sw3, g_s3h, DIM, SHID, t % 32, t / 32);
    } else {
        t -= T_S3;
        cvt_tile(sw2, g_s2h, SHID, DIM, t % 48, t / 48);
    }
}

// ---------------- fused gate + x->fp16 conversion ------------------------------
// One warp per token: stream the row once (float4), emit fp16 copy, compute
// 8 gate logits, softmax, top-2, compact.
__global__ void gate_kernel(const float* __restrict__ x, const float* __restrict__ gw) {
    int tok  = (blockIdx.x * blockDim.x + threadIdx.x) >> 5;
    int lane = threadIdx.x & 31;
    if (tok >= TOK) return;
    const float4* xr = reinterpret_cast<const float4*>(x + (size_t)tok * DIM);
    uint2* xo = reinterpret_cast<uint2*>(g_xh + (size_t)tok * DIM);
    float acc[NEXP];
#pragma unroll
    for (int e = 0; e < NEXP; e++) acc[e] = 0.f;
#pragma unroll
    for (int j = 0; j < 8; j++) {
        int q = lane + j * 32;               // float4 index within row
        float4 v = xr[q];
        uint2 ph;
        ph.x = pack2(__float2half(v.x), __float2half(v.y));
        ph.y = pack2(__float2half(v.z), __float2half(v.w));
        xo[q] = ph;
        int d = q * 4;
#pragma unroll
        for (int e = 0; e < NEXP; e++) {
            const float* gr = gw + e * DIM + d;
            acc[e] = fmaf(v.x, gr[0], acc[e]);
            acc[e] = fmaf(v.y, gr[1], acc[e]);
            acc[e] = fmaf(v.z, gr[2], acc[e]);
            acc[e] = fmaf(v.w, gr[3], acc[e]);
        }
    }
#pragma unroll
    for (int e = 0; e < NEXP; e++)
#pragma unroll
        for (int off = 16; off > 0; off >>= 1)
            acc[e] += __shfl_xor_sync(0xffffffffu, acc[e], off);
    if (lane == 0) {
        float mx = acc[0];
#pragma unroll
        for (int e = 1; e < NEXP; e++) mx = fmaxf(mx, acc[e]);
        float p[NEXP], s = 0.f;
#pragma unroll
        for (int e = 0; e < NEXP; e++) { p[e] = expf(acc[e] - mx); s += p[e]; }
        float inv = 1.f / s;
#pragma unroll
        for (int e = 0; e < NEXP; e++) p[e] *= inv;
        int i1 = 0;
#pragma unroll
        for (int e = 1; e < NEXP; e++) if (p[e] > p[i1]) i1 = e;
        int i2 = (i1 == 0) ? 1 : 0;
#pragma unroll
        for (int e = 0; e < NEXP; e++) if (e != i1 && p[e] > p[i2]) i2 = e;
        int pos1 = atomicAdd(&g_cnt[i1], 1);
        g_idx[i1 * TOK + pos1] = tok;  g_wgt[i1 * TOK + pos1] = p[i1];
        g_slot[2 * tok] = i1 * TOK + pos1;
        int pos2 = atomicAdd(&g_cnt[i2], 1);
        g_idx[i2 * TOK + pos2] = tok;  g_wgt[i2 * TOK + pos2] = p[i2];
        g_slot[2 * tok + 1] = i2 * TOK + pos2;
    }
}

// ---------------- GEMM1: fused SwiGLU up-proj (merged routed+shared) -----------
// grid.z in [0,8]: z<8 routed expert z (N=EHID, gathered rows), z==8 shared
// (N=SHID, identity rows). BM=128, BN=64 per B-matrix, BK=32, 256 threads.
#define G1_S_AH   0
#define G1_S_B1H  5120
#define G1_S_B3H  7680
#define G1_STG    10240
#define G1_SMEM   (2 * G1_STG * 2)   // 40960 B

__global__ void __launch_bounds__(256, 2)
gemm1_kernel() {
    const int K = DIM;
    int z = blockIdx.z;
    bool sh = (z == NEXP);
    int M = sh ? TOK : g_cnt[z];
    int N = sh ? SHID : EHID;
    int rowBlock = blockIdx.y * 128;
    if (rowBlock >= M) return;
    int colBlock = blockIdx.x * 64;
    if (colBlock >= N) return;
    const fp16* B1 = sh ? g_s1h : g_w1h + (size_t)z * EHID * DIM;
    const fp16* B3 = sh ? g_s3h : g_w3h + (size_t)z * EHID * DIM;
    fp16* H        = sh ? g_hsh : g_hh  + (size_t)z * TOK * EHID;

    extern __shared__ __align__(16) fp16 sm1[];
    uint32_t sb0 = smem_u32(sm1);

    int tid = threadIdx.x, lane = tid & 31, warp = tid >> 5;
    int wm = warp >> 2, wn = warp & 3;

    int ra = tid >> 1, ka = (tid & 1) * 16;
    bool aval = (rowBlock + ra) < M;
    int asrc = aval ? (sh ? rowBlock + ra : g_idx[z * TOK + rowBlock + ra]) : 0;
    const fp16* aph = g_xh + (size_t)asrc * K + ka;
    uint32_t adst = (uint32_t)(ra * LDH + ka) * 2;

    int rb = tid >> 2, kb = (tid & 3) * 8;
    const fp16* b1p = B1 + (size_t)(colBlock + rb) * K + kb;
    const fp16* b3p = B3 + (size_t)(colBlock + rb) * K + kb;
    uint32_t bdst = (uint32_t)(rb * LDH + kb) * 2;

    auto load_stage = [&](int s, int k0) {
        uint32_t sb = sb0 + (uint32_t)s * G1_STG * 2;
        cp16(sb + G1_S_AH * 2 + adst,      aph + k0,     aval);
        cp16(sb + G1_S_AH * 2 + adst + 16, aph + k0 + 8, aval);
        cp16(sb + G1_S_B1H * 2 + bdst, b1p + k0, true);
        cp16(sb + G1_S_B3H * 2 + bdst, b3p + k0, true);
    };

    int lrow = lane & 15, lkA = (lane >> 4) * 8;
    uint32_t aOff[4];
#pragma unroll
    for (int mi = 0; mi < 4; mi++) {
        int r = wm * 64 + mi * 16 + lrow;
        aOff[mi] = (uint32_t)(G1_S_AH + r * LDH + lkA) * 2;
    }
    int nloc = (lane & 7) | ((lane & 16) >> 1);
    int lkB  = ((lane >> 3) & 1) * 8;
    uint32_t bRow = (uint32_t)((wn * 16 + nloc) * LDH + lkB) * 2;
    uint32_t b1Off = G1_S_B1H * 2 + bRow;
    uint32_t b3Off = G1_S_B3H * 2 + bRow;

    float acc1[4][2][4], acc3[4][2][4];
#pragma unroll
    for (int i = 0; i < 4; i++)
#pragma unroll
        for (int j = 0; j < 2; j++)
#pragma unroll
            for (int r = 0; r < 4; r++) { acc1[i][j][r] = 0.f; acc3[i][j][r] = 0.f; }

    load_stage(0, 0);
    CP_COMMIT();
    const int nIter = K / 32;
    for (int i = 0; i < nIter; i++) {
        if (i + 1 < nIter) { load_stage((i + 1) & 1, (i + 1) * 32); CP_COMMIT(); CP_WAIT1(); }
        else               { CP_WAIT0(); }
        __syncthreads();
        uint32_t sb = sb0 + (uint32_t)(i & 1) * G1_STG * 2;
#pragma unroll
        for (int ks = 0; ks < 2; ks++) {
            uint32_t ko = (uint32_t)ks * 32;
            uint32_t ah[4][4];
#pragma unroll
            for (int mi = 0; mi < 4; mi++)
                LDSM4(ah[mi], sb + aOff[mi] + ko);
            uint32_t b1[4], b3[4];
            LDSM4(b1, sb + b1Off + ko);
            LDSM4(b3, sb + b3Off + ko);
#pragma unroll
            for (int mi = 0; mi < 4; mi++)
#pragma unroll
                for (int nf = 0; nf < 2; nf++) {
                    mma_f16(acc1[mi][nf], ah[mi], b1[2*nf], b1[2*nf+1]);
                    mma_f16(acc3[mi][nf], ah[mi], b3[2*nf], b3[2*nf+1]);
                }
        }
        __syncthreads();
    }

    int rr = lane >> 2, cc = (lane & 3) * 2;
#pragma unroll
    for (int mi = 0; mi < 4; mi++) {
        int gmb = rowBlock + wm * 64 + mi * 16 + rr;
#pragma unroll
        for (int nf = 0; nf < 2; nf++) {
            int col = colBlock + wn * 16 + nf * 8 + cc;
#pragma unroll
            for (int hf = 0; hf < 2; hf++) {
                int gm = gmb + hf * 8;
                if (gm < M) {
                    float v1a = acc1[mi][nf][hf*2], v1b = acc1[mi][nf][hf*2+1];
                    float v3a = acc3[mi][nf][hf*2], v3b = acc3[mi][nf][hf*2+1];
                    float h0 = v1a / (1.f + expf(-v1a)) * v3a;
                    float h1 = v1b / (1.f + expf(-v1b)) * v3b;
                    *reinterpret_cast<uint32_t*>(H + (size_t)gm * N + col) =
                        pack2(__float2half(h0), __float2half(h1));
                }
            }
        }
    }
}

// ---------------- GEMM2: down-projection (merged) ------------------------------
#define G2_S_AH  0
#define G2_S_BH  5120
#define G2_STG   7680
#define G2_SMEM  (2 * G2_STG * 2)    // 30720 B

__global__ void __launch_bounds__(256, 2)
gemm2_kernel(float* __restrict__ out) {
    int z = blockIdx.z;
    bool sh = (z == NEXP);
    int M = sh ? TOK : g_cnt[z];
    int K = sh ? SHID : EHID;
    int rowBlock = blockIdx.y * 128;
    if (rowBlock >= M) return;
    int colBlock = blockIdx.x * 64;
    const fp16* A = sh ? g_hsh : g_hh + (size_t)z * TOK * EHID;
    const fp16* B = sh ? g_s2h : g_w2h + (size_t)z * DIM * EHID;
    float* Y      = sh ? out   : g_yp  + (size_t)z * TOK * DIM;

    extern __shared__ __align__(16) fp16 sm2[];
    uint32_t sb0 = smem_u32(sm2);

    int tid = threadIdx.x, lane = tid & 31, warp = tid >> 5;
    int wm = warp >> 2, wn = warp & 3;

    int ra = tid >> 1, ka = (tid & 1) * 16;
    bool aval = (rowBlock + ra) < M;
    const fp16* aph = A + (size_t)(aval ? rowBlock + ra : 0) * K + ka;
    uint32_t adst = (uint32_t)(ra * LDH + ka) * 2;

    int rb = tid >> 2, kb = (tid & 3) * 8;
    const fp16* bp = B + (size_t)(colBlock + rb) * K + kb;
    uint32_t bdst = (uint32_t)(rb * LDH + kb) * 2;

    auto load_stage = [&](int s, int k0) {
        uint32_t sb = sb0 + (uint32_t)s * G2_STG * 2;
        cp16(sb + G2_S_AH * 2 + adst,      aph + k0,     aval);
        cp16(sb + G2_S_AH * 2 + adst + 16, aph + k0 + 8, aval);
        cp16(sb + G2_S_BH * 2 + bdst, bp + k0, true);
    };

    int lrow = lane & 15, lkA = (lane >> 4) * 8;
    uint32_t aOff[4];
#pragma unroll
    for (int mi = 0; mi < 4; mi++) {
        int r = wm * 64 + mi * 16 + lrow;
        aOff[mi] = (uint32_t)(G2_S_AH + r * LDH + lkA) * 2;
    }
    int nloc = (lane & 7) | ((lane & 16) >> 1);
    int lkB  = ((lane >> 3) & 1) * 8;
    uint32_t bOff = (uint32_t)(G2_S_BH + (wn * 16 + nloc) * LDH + lkB) * 2;

    float acc[4][2][4];
#pragma unroll
    for (int i = 0; i < 4; i++)
#pragma unroll
        for (int j = 0; j < 2; j++)
#pragma unroll
            for (int r = 0; r < 4; r++) acc[i][j][r] = 0.f;

    load_stage(0, 0);
    CP_COMMIT();
    const int nIter = K / 32;
    for (int i = 0; i < nIter; i++) {
        if (i + 1 < nIter) { load_stage((i + 1) & 1, (i + 1) * 32); CP_COMMIT(); CP_WAIT1(); }
        else               { CP_WAIT0(); }
        __syncthreads();
        uint32_t sb = sb0 + (uint32_t)(i & 1) * G2_STG * 2;
#pragma unroll
        for (int ks = 0; ks < 2; ks++) {
            uint32_t ko = (uint32_t)ks * 32;
            uint32_t ah[4][4];
#pragma unroll
            for (int mi = 0; mi < 4; mi++)
                LDSM4(ah[mi], sb + aOff[mi] + ko);
            uint32_t b[4];
            LDSM4(b, sb + bOff + ko);
#pragma unroll
            for (int mi = 0; mi < 4; mi++)
#pragma unroll
                for (int nf = 0; nf < 2; nf++)
                    mma_f16(acc[mi][nf], ah[mi], b[2*nf], b[2*nf+1]);
        }
        __syncthreads();
    }

    int rr = lane >> 2, cc = (lane & 3) * 2;
#pragma unroll
    for (int mi = 0; mi < 4; mi++) {
        int gmb = rowBlock + wm * 64 + mi * 16 + rr;
#pragma unroll
        for (int hf = 0; hf < 2; hf++) {
            int gm = gmb + hf * 8;
            if (gm < M) {
                float w = sh ? 1.0f : g_wgt[z * TOK + gm];
                float* dst = Y + (size_t)gm * DIM;
#pragma unroll
                for (int nf = 0; nf < 2; nf++) {
                    int col = colBlock + wn * 16 + nf * 8 + cc;
                    float2 v;
                    v.x = w * acc[mi][nf][hf*2];
                    v.y = w * acc[mi][nf][hf*2+1];
                    *reinterpret_cast<float2*>(dst + col) = v;
                }
            }
        }
    }
}

// out[t] += yp[slot0(t)] + yp[slot1(t)]
__global__ void combine_kernel(float* __restrict__ out) {
    int t = blockIdx.x;
    int d = threadIdx.x;
    int s0 = g_slot[2 * t], s1 = g_slot[2 * t + 1];
    float4* o = reinterpret_cast<float4*>(out) + (size_t)t * 256 + d;
    const float4 a  = *o;
    const float4 b0 = reinterpret_cast<const float4*>(g_yp)[(size_t)s0 * 256 + d];
    const float4 b1 = reinterpret_cast<const float4*>(g_yp)[(size_t)s1 * 256 + d];
    float4 r;
    r.x = a.x + (b0.x + b1.x);
    r.y = a.y + (b0.y + b1.y);
    r.z = a.z + (b0.z + b1.z);
    r.w = a.w + (b0.w + b1.w);
    *o = r;
}

// ---------------- launcher -----------------------------------------------------
extern "C" void kernel_launch(void* const* d_in, const int* in_sizes, int n_in,
                              void* d_out, int out_size) {
    const float* x   = (const float*)d_in[0];
    const float* gw  = (const float*)d_in[1];
    const float* w1  = (const float*)d_in[2];
    const float* w2  = (const float*)d_in[3];
    const float* w3  = (const float*)d_in[4];
    const float* sw1 = (const float*)d_in[5];
    const float* sw2 = (const float*)d_in[6];
    const float* sw3 = (const float*)d_in[7];
    float* out = (float*)d_out;
    (void)in_sizes; (void)n_in; (void)out_size;

    cudaFuncSetAttribute(gemm1_kernel, cudaFuncAttributeMaxDynamicSharedMemorySize, G1_SMEM);
    cudaFuncSetAttribute(gemm2_kernel, cudaFuncAttributeMaxDynamicSharedMemorySize, G2_SMEM);

    // conversions (also zeroes g_cnt in block 0)
    cvt_all_kernel<<<T_ALL, 256>>>(w1, w3, w2, sw1, sw3, sw2);
    // fused gate + x->fp16
    gate_kernel<<<TOK / 8, 256>>>(x, gw);

    // merged up-proj: z<8 routed experts, z==8 shared expert
    gemm1_kernel<<<dim3(EHID / 64, TOK / 128, NEXP + 1), 256, G1_SMEM>>>();
    // merged down-proj: shared writes d_out, routed writes yp partials
    gemm2_kernel<<<dim3(DIM / 64, TOK / 128, NEXP + 1), 256, G2_SMEM>>>(out);

    combine_kernel<<<TOK, 256>>>(out);
}

// round 11
// speedup vs baseline: 7.3621x; 1.1198x over previous
#include <cuda_runtime.h>
#include <cuda_fp16.h>
#include <math.h>
#include <stdint.h>

#define TOK   4096
#define DIM   1024
#define NEXP  8
#define EHID  2816
#define SHID  1536
#define LDH   40      // smem row stride in fp16 elems (32 data + 8 pad)

typedef __half fp16;

// ---------------- scratch (device globals) ----------------------------------
__device__ fp16  g_xh [(size_t)TOK*DIM];
__device__ fp16  g_w1h[(size_t)NEXP*EHID*DIM];
__device__ fp16  g_w3h[(size_t)NEXP*EHID*DIM];
__device__ fp16  g_w2h[(size_t)NEXP*DIM*EHID];
__device__ fp16  g_s1h[(size_t)SHID*DIM];
__device__ fp16  g_s3h[(size_t)SHID*DIM];
__device__ fp16  g_s2h[(size_t)DIM*SHID];
__device__ fp16  g_hh [(size_t)NEXP*TOK*EHID];   // routed hidden (fp16)
__device__ fp16  g_hsh[(size_t)TOK*SHID];        // shared hidden
__device__ float g_yp [(size_t)NEXP*TOK*DIM];
__device__ int   g_cnt[NEXP];
__device__ int   g_idx[NEXP*TOK];
__device__ float g_wgt[NEXP*TOK];
__device__ int   g_slot[TOK*2];

// ---------------- helpers ----------------------------------------------------
__device__ __forceinline__ uint32_t smem_u32(const void* p) {
    uint32_t a;
    asm("{ .reg .u64 t; cvta.to.shared.u64 t, %1; cvt.u32.u64 %0, t; }"
        : "=r"(a) : "l"(p));
    return a;
}
__device__ __forceinline__ void cp16(uint32_t saddr, const void* g, bool valid) {
    int sz = valid ? 16 : 0;
    asm volatile("cp.async.cg.shared.global [%0], [%1], 16, %2;"
                 :: "r"(saddr), "l"(g), "r"(sz));
}
#define CP_COMMIT() asm volatile("cp.async.commit_group;")
#define CP_WAIT1()  asm volatile("cp.async.wait_group 1;")
#define CP_WAIT0()  asm volatile("cp.async.wait_group 0;")

#define LDSM4(r, addr) \
    asm volatile("ldmatrix.sync.aligned.m8n8.x4.shared.b16 {%0,%1,%2,%3}, [%4];" \
        : "=r"((r)[0]), "=r"((r)[1]), "=r"((r)[2]), "=r"((r)[3]) : "r"(addr))

__device__ __forceinline__ void mma_f16(float d[4], const uint32_t a[4],
                                        uint32_t b0, uint32_t b1) {
    asm volatile(
        "mma.sync.aligned.m16n8k16.row.col.f32.f16.f16.f32 "
        "{%0,%1,%2,%3},{%4,%5,%6,%7},{%8,%9},{%0,%1,%2,%3};"
        : "+f"(d[0]), "+f"(d[1]), "+f"(d[2]), "+f"(d[3])
        : "r"(a[0]), "r"(a[1]), "r"(a[2]), "r"(a[3]), "r"(b0), "r"(b1));
}

__device__ __forceinline__ uint32_t pack2(fp16 a, fp16 b) {
    return ((uint32_t)__half_as_ushort(b) << 16) | (uint32_t)__half_as_ushort(a);
}

// ---------------- merged weight transpose+convert (also zeroes g_cnt) ----------
#define T_W1   22528
#define T_W3   45056
#define T_W2   67584
#define T_S1   69120
#define T_S3   70656
#define T_ALL  72192

__device__ __forceinline__ void cvt_tile(const float* __restrict__ in,
                                         fp16* __restrict__ out,
                                         int K, int N, int kt, int nt) {
    __shared__ float tile[32][33];
    int k0 = kt * 32, n0 = nt * 32;
    int idx = threadIdx.x;
    int tx = idx & 31, ty = idx >> 5;
#pragma unroll
    for (int j = 0; j < 4; j++)
        tile[ty + 8 * j][tx] = in[(size_t)(k0 + ty + 8 * j) * N + (n0 + tx)];
    __syncthreads();
    int nl = idx >> 3, kq = (idx & 7) * 4;
    float v0 = tile[kq + 0][nl], v1 = tile[kq + 1][nl];
    float v2 = tile[kq + 2][nl], v3 = tile[kq + 3][nl];
    uint2 o;
    o.x = pack2(__float2half(v0), __float2half(v1));
    o.y = pack2(__float2half(v2), __float2half(v3));
    *reinterpret_cast<uint2*>(out + (size_t)(n0 + nl) * K + k0 + kq) = o;
}

__global__ void __launch_bounds__(256)
cvt_all_kernel(const float* __restrict__ w1, const float* __restrict__ w3,
               const float* __restrict__ w2, const float* __restrict__ sw1,
               const float* __restrict__ sw3, const float* __restrict__ sw2) {
    int t = blockIdx.x;
    if (t == 0 && threadIdx.x < NEXP) g_cnt[threadIdx.x] = 0;
    if (t < T_W1) {
        int z = t / (32 * 88), r = t % (32 * 88);
        cvt_tile(w1 + (size_t)z * DIM * EHID, g_w1h + (size_t)z * EHID * DIM,
                 DIM, EHID, r % 32, r / 32);
    } else if (t < T_W3) {
        t -= T_W1;
        int z = t / (32 * 88), r = t % (32 * 88);
        cvt_tile(w3 + (size_t)z * DIM * EHID, g_w3h + (size_t)z * EHID * DIM,
                 DIM, EHID, r % 32, r / 32);
    } else if (t < T_W2) {
        t -= T_W3;
        int z = t / (88 * 32), r = t % (88 * 32);
        cvt_tile(w2 + (size_t)z * EHID * DIM, g_w2h + (size_t)z * DIM * EHID,
                 EHID, DIM, r % 88, r / 88);
    } else if (t < T_S1) {
        t -= T_W2;
        cvt_tile(sw1, g_s1h, DIM, SHID, t % 32, t / 32);
    } else if (t < T_S3) {
        t -= T_S1;
        cvt_tile(sw3, g_s3h, DIM, SHID, t % 32, t / 32);
    } else {
        t -= T_S3;
        cvt_tile(sw2, g_s2h, SHID, DIM, t % 48, t / 48);
    }
}

// ---------------- fused gate + x->fp16 conversion ------------------------------
__global__ void gate_kernel(const float* __restrict__ x, const float* __restrict__ gw) {
    int tok  = (blockIdx.x * blockDim.x + threadIdx.x) >> 5;
    int lane = threadIdx.x & 31;
    if (tok >= TOK) return;
    const float4* xr = reinterpret_cast<const float4*>(x + (size_t)tok * DIM);
    uint2* xo = reinterpret_cast<uint2*>(g_xh + (size_t)tok * DIM);
    float acc[NEXP];
#pragma unroll
    for (int e = 0; e < NEXP; e++) acc[e] = 0.f;
#pragma unroll
    for (int j = 0; j < 8; j++) {
        int q = lane + j * 32;
        float4 v = xr[q];
        uint2 ph;
        ph.x = pack2(__float2half(v.x), __float2half(v.y));
        ph.y = pack2(__float2half(v.z), __float2half(v.w));
        xo[q] = ph;
        int d = q * 4;
#pragma unroll
        for (int e = 0; e < NEXP; e++) {
            const float* gr = gw + e * DIM + d;
            acc[e] = fmaf(v.x, gr[0], acc[e]);
            acc[e] = fmaf(v.y, gr[1], acc[e]);
            acc[e] = fmaf(v.z, gr[2], acc[e]);
            acc[e] = fmaf(v.w, gr[3], acc[e]);
        }
    }
#pragma unroll
    for (int e = 0; e < NEXP; e++)
#pragma unroll
        for (int off = 16; off > 0; off >>= 1)
            acc[e] += __shfl_xor_sync(0xffffffffu, acc[e], off);
    if (lane == 0) {
        float mx = acc[0];
#pragma unroll
        for (int e = 1; e < NEXP; e++) mx = fmaxf(mx, acc[e]);
        float p[NEXP], s = 0.f;
#pragma unroll
        for (int e = 0; e < NEXP; e++) { p[e] = expf(acc[e] - mx); s += p[e]; }
        float inv = 1.f / s;
#pragma unroll
        for (int e = 0; e < NEXP; e++) p[e] *= inv;
        int i1 = 0;
#pragma unroll
        for (int e = 1; e < NEXP; e++) if (p[e] > p[i1]) i1 = e;
        int i2 = (i1 == 0) ? 1 : 0;
#pragma unroll
        for (int e = 0; e < NEXP; e++) if (e != i1 && p[e] > p[i2]) i2 = e;
        int pos1 = atomicAdd(&g_cnt[i1], 1);
        g_idx[i1 * TOK + pos1] = tok;  g_wgt[i1 * TOK + pos1] = p[i1];
        g_slot[2 * tok] = i1 * TOK + pos1;
        int pos2 = atomicAdd(&g_cnt[i2], 1);
        g_idx[i2 * TOK + pos2] = tok;  g_wgt[i2 * TOK + pos2] = p[i2];
        g_slot[2 * tok + 1] = i2 * TOK + pos2;
    }
}

// ---------------- GEMM1: fused SwiGLU up-proj (3-stage pipeline) ----------------
// grid.z in [0,8]: z<8 routed expert z, z==8 shared. BM=128, BN=64/matrix, BK=32.
#define G1_S_AH   0
#define G1_S_B1H  5120
#define G1_S_B3H  7680
#define G1_STG    10240
#define G1_SMEM   (3 * G1_STG * 2)   // 61440 B

__global__ void __launch_bounds__(256, 2)
gemm1_kernel() {
    const int K = DIM;
    int z = blockIdx.z;
    bool sh = (z == NEXP);
    int M = sh ? TOK : g_cnt[z];
    int N = sh ? SHID : EHID;
    int rowBlock = blockIdx.y * 128;
    if (rowBlock >= M) return;
    int colBlock = blockIdx.x * 64;
    if (colBlock >= N) return;
    const fp16* B1 = sh ? g_s1h : g_w1h + (size_t)z * EHID * DIM;
    const fp16* B3 = sh ? g_s3h : g_w3h + (size_t)z * EHID * DIM;
    fp16* H        = sh ? g_hsh : g_hh  + (size_t)z * TOK * EHID;

    extern __shared__ __align__(16) fp16 sm1[];
    uint32_t sb0 = smem_u32(sm1);

    int tid = threadIdx.x, lane = tid & 31, warp = tid >> 5;
    int wm = warp >> 2, wn = warp & 3;

    int ra = tid >> 1, ka = (tid & 1) * 16;
    bool aval = (rowBlock + ra) < M;
    int asrc = aval ? (sh ? rowBlock + ra : g_idx[z * TOK + rowBlock + ra]) : 0;
    const fp16* aph = g_xh + (size_t)asrc * K + ka;
    uint32_t adst = (uint32_t)(ra * LDH + ka) * 2;

    int rb = tid >> 2, kb = (tid & 3) * 8;
    const fp16* b1p = B1 + (size_t)(colBlock + rb) * K + kb;
    const fp16* b3p = B3 + (size_t)(colBlock + rb) * K + kb;
    uint32_t bdst = (uint32_t)(rb * LDH + kb) * 2;

    auto load_stage = [&](int s, int k0) {
        uint32_t sb = sb0 + (uint32_t)s * G1_STG * 2;
        cp16(sb + G1_S_AH * 2 + adst,      aph + k0,     aval);
        cp16(sb + G1_S_AH * 2 + adst + 16, aph + k0 + 8, aval);
        cp16(sb + G1_S_B1H * 2 + bdst, b1p + k0, true);
        cp16(sb + G1_S_B3H * 2 + bdst, b3p + k0, true);
    };

    int lrow = lane & 15, lkA = (lane >> 4) * 8;
    uint32_t aOff[4];
#pragma unroll
    for (int mi = 0; mi < 4; mi++) {
        int r = wm * 64 + mi * 16 + lrow;
        aOff[mi] = (uint32_t)(G1_S_AH + r * LDH + lkA) * 2;
    }
    int nloc = (lane & 7) | ((lane & 16) >> 1);
    int lkB  = ((lane >> 3) & 1) * 8;
    uint32_t bRow = (uint32_t)((wn * 16 + nloc) * LDH + lkB) * 2;
    uint32_t b1Off = G1_S_B1H * 2 + bRow;
    uint32_t b3Off = G1_S_B3H * 2 + bRow;

    float acc1[4][2][4], acc3[4][2][4];
#pragma unroll
    for (int i = 0; i < 4; i++)
#pragma unroll
        for (int j = 0; j < 2; j++)
#pragma unroll
            for (int r = 0; r < 4; r++) { acc1[i][j][r] = 0.f; acc3[i][j][r] = 0.f; }

    const int nIter = K / 32;
    load_stage(0, 0);
    CP_COMMIT();
    load_stage(1, 32);
    CP_COMMIT();
    int cur = 0, pre = 2;
    for (int i = 0; i < nIter; i++) {
        if (i < nIter - 1) { CP_WAIT1(); } else { CP_WAIT0(); }
        __syncthreads();
        if (i + 2 < nIter) { load_stage(pre, (i + 2) * 32); CP_COMMIT(); }
        uint32_t sb = sb0 + (uint32_t)cur * G1_STG * 2;
#pragma unroll
        for (int ks = 0; ks < 2; ks++) {
            uint32_t ko = (uint32_t)ks * 32;
            uint32_t ah[4][4];
#pragma unroll
            for (int mi = 0; mi < 4; mi++)
                LDSM4(ah[mi], sb + aOff[mi] + ko);
            uint32_t b1[4], b3[4];
            LDSM4(b1, sb + b1Off + ko);
            LDSM4(b3, sb + b3Off + ko);
#pragma unroll
            for (int mi = 0; mi < 4; mi++)
#pragma unroll
                for (int nf = 0; nf < 2; nf++) {
                    mma_f16(acc1[mi][nf], ah[mi], b1[2*nf], b1[2*nf+1]);
                    mma_f16(acc3[mi][nf], ah[mi], b3[2*nf], b3[2*nf+1]);
                }
        }
        cur = (cur == 2) ? 0 : cur + 1;
        pre = (pre == 2) ? 0 : pre + 1;
    }

    int rr = lane >> 2, cc = (lane & 3) * 2;
#pragma unroll
    for (int mi = 0; mi < 4; mi++) {
        int gmb = rowBlock + wm * 64 + mi * 16 + rr;
#pragma unroll
        for (int nf = 0; nf < 2; nf++) {
            int col = colBlock + wn * 16 + nf * 8 + cc;
#pragma unroll
            for (int hf = 0; hf < 2; hf++) {
                int gm = gmb + hf * 8;
                if (gm < M) {
                    float v1a = acc1[mi][nf][hf*2], v1b = acc1[mi][nf][hf*2+1];
                    float v3a = acc3[mi][nf][hf*2], v3b = acc3[mi][nf][hf*2+1];
                    float h0 = v1a / (1.f + expf(-v1a)) * v3a;
                    float h1 = v1b / (1.f + expf(-v1b)) * v3b;
                    *reinterpret_cast<uint32_t*>(H + (size_t)gm * N + col) =
                        pack2(__float2half(h0), __float2half(h1));
                }
            }
        }
    }
}

// ---------------- GEMM2: down-projection (BN=128, 3-stage) ----------------------
// grid.z in [0,8]; BM=128, BN=128, BK=32, 256 threads (8 warps 2m x 4n, 64x32).
#define G2_S_A   0
#define G2_S_B   5120
#define G2_STG   10240
#define G2_SMEM  (3 * G2_STG * 2)    // 61440 B

__global__ void __launch_bounds__(256, 2)
gemm2_kernel(float* __restrict__ out) {
    int z = blockIdx.z;
    bool sh = (z == NEXP);
    int M = sh ? TOK : g_cnt[z];
    int K = sh ? SHID : EHID;
    int rowBlock = blockIdx.y * 128;
    if (rowBlock >= M) return;
    int colBlock = blockIdx.x * 128;
    const fp16* A = sh ? g_hsh : g_hh + (size_t)z * TOK * EHID;
    const fp16* B = sh ? g_s2h : g_w2h + (size_t)z * DIM * EHID;
    float* Y      = sh ? out   : g_yp  + (size_t)z * TOK * DIM;

    extern __shared__ __align__(16) fp16 sm2[];
    uint32_t sb0 = smem_u32(sm2);

    int tid = threadIdx.x, lane = tid & 31, warp = tid >> 5;
    int wm = warp >> 2, wn = warp & 3;

    int ra = tid >> 1, ka = (tid & 1) * 16;
    bool aval = (rowBlock + ra) < M;
    const fp16* aph = A + (size_t)(aval ? rowBlock + ra : 0) * K + ka;
    const fp16* bph = B + (size_t)(colBlock + ra) * K + ka;
    uint32_t adst = (uint32_t)(ra * LDH + ka) * 2;

    auto load_stage = [&](int s, int k0) {
        uint32_t sb = sb0 + (uint32_t)s * G2_STG * 2;
        cp16(sb + G2_S_A * 2 + adst,      aph + k0,     aval);
        cp16(sb + G2_S_A * 2 + adst + 16, aph + k0 + 8, aval);
        cp16(sb + G2_S_B * 2 + adst,      bph + k0,     true);
        cp16(sb + G2_S_B * 2 + adst + 16, bph + k0 + 8, true);
    };

    int lrow = lane & 15, lkA = (lane >> 4) * 8;
    uint32_t aOff[4];
#pragma unroll
    for (int mi = 0; mi < 4; mi++) {
        int r = wm * 64 + mi * 16 + lrow;
        aOff[mi] = (uint32_t)(G2_S_A + r * LDH + lkA) * 2;
    }
    int nloc = (lane & 7) | ((lane & 16) >> 1);
    int lkB  = ((lane >> 3) & 1) * 8;
    uint32_t bOff[2];
#pragma unroll
    for (int ng = 0; ng < 2; ng++) {
        int n = wn * 32 + ng * 16 + nloc;
        bOff[ng] = (uint32_t)(G2_S_B + n * LDH + lkB) * 2;
    }

    float acc[4][4][4];
#pragma unroll
    for (int i = 0; i < 4; i++)
#pragma unroll
        for (int j = 0; j < 4; j++)
#pragma unroll
            for (int r = 0; r < 4; r++) acc[i][j][r] = 0.f;

    const int nIter = K / 32;
    load_stage(0, 0);
    CP_COMMIT();
    load_stage(1, 32);
    CP_COMMIT();
    int cur = 0, pre = 2;
    for (int i = 0; i < nIter; i++) {
        if (i < nIter - 1) { CP_WAIT1(); } else { CP_WAIT0(); }
        __syncthreads();
        if (i + 2 < nIter) { load_stage(pre, (i + 2) * 32); CP_COMMIT(); }
        uint32_t sb = sb0 + (uint32_t)cur * G2_STG * 2;
#pragma unroll
        for (int ks = 0; ks < 2; ks++) {
            uint32_t ko = (uint32_t)ks * 32;
            uint32_t ah[4][4];
#pragma unroll
            for (int mi = 0; mi < 4; mi++)
                LDSM4(ah[mi], sb + aOff[mi] + ko);
            uint32_t b[2][4];
#pragma unroll
            for (int ng = 0; ng < 2; ng++)
                LDSM4(b[ng], sb + bOff[ng] + ko);
#pragma unroll
            for (int mi = 0; mi < 4; mi++)
#pragma unroll
                for (int nf = 0; nf < 4; nf++)
                    mma_f16(acc[mi][nf], ah[mi], b[nf >> 1][(nf & 1) * 2],
                            b[nf >> 1][(nf & 1) * 2 + 1]);
        }
        cur = (cur == 2) ? 0 : cur + 1;
        pre = (pre == 2) ? 0 : pre + 1;
    }

    int rr = lane >> 2, cc = (lane & 3) * 2;
#pragma unroll
    for (int mi = 0; mi < 4; mi++) {
        int gmb = rowBlock + wm * 64 + mi * 16 + rr;
#pragma unroll
        for (int hf = 0; hf < 2; hf++) {
            int gm = gmb + hf * 8;
            if (gm < M) {
                float w = sh ? 1.0f : g_wgt[z * TOK + gm];
                float* dst = Y + (size_t)gm * DIM;
#pragma unroll
                for (int nf = 0; nf < 4; nf++) {
                    int col = colBlock + wn * 32 + nf * 8 + cc;
                    float2 v;
                    v.x = w * acc[mi][nf][hf*2];
                    v.y = w * acc[mi][nf][hf*2+1];
                    *reinterpret_cast<float2*>(dst + col) = v;
                }
            }
        }
    }
}

// out[t] += yp[slot0(t)] + yp[slot1(t)]
__global__ void combine_kernel(float* __restrict__ out) {
    int t = blockIdx.x;
    int d = threadIdx.x;
    int s0 = g_slot[2 * t], s1 = g_slot[2 * t + 1];
    float4* o = reinterpret_cast<float4*>(out) + (size_t)t * 256 + d;
    const float4 a  = *o;
    const float4 b0 = reinterpret_cast<const float4*>(g_yp)[(size_t)s0 * 256 + d];
    const float4 b1 = reinterpret_cast<const float4*>(g_yp)[(size_t)s1 * 256 + d];
    float4 r;
    r.x = a.x + (b0.x + b1.x);
    r.y = a.y + (b0.y + b1.y);
    r.z = a.z + (b0.z + b1.z);
    r.w = a.w + (b0.w + b1.w);
    *o = r;
}

// ---------------- launcher -----------------------------------------------------
extern "C" void kernel_launch(void* const* d_in, const int* in_sizes, int n_in,
                              void* d_out, int out_size) {
    const float* x   = (const float*)d_in[0];
    const float* gw  = (const float*)d_in[1];
    const float* w1  = (const float*)d_in[2];
    const float* w2  = (const float*)d_in[3];
    const float* w3  = (const float*)d_in[4];
    const float* sw1 = (const float*)d_in[5];
    const float* sw2 = (const float*)d_in[6];
    const float* sw3 = (const float*)d_in[7];
    float* out = (float*)d_out;
    (void)in_sizes; (void)n_in; (void)out_size;

    cudaFuncSetAttribute(gemm1_kernel, cudaFuncAttributeMaxDynamicSharedMemorySize, G1_SMEM);
    cudaFuncSetAttribute(gemm2_kernel, cudaFuncAttributeMaxDynamicSharedMemorySize, G2_SMEM);

    // conversions (also zeroes g_cnt in block 0)
    cvt_all_kernel<<<T_ALL, 256>>>(w1, w3, w2, sw1, sw3, sw2);
    // fused gate + x->fp16
    gate_kernel<<<TOK / 8, 256>>>(x, gw);

    // merged up-proj: z<8 routed experts, z==8 shared expert
    gemm1_kernel<<<dim3(EHID / 64, TOK / 128, NEXP + 1), 256, G1_SMEM>>>();
    // merged down-proj: shared writes d_out, routed writes yp partials
    gemm2_kernel<<<dim3(DIM / 128, TOK / 128, NEXP + 1), 256, G2_SMEM>>>(out);

    combine_kernel<<<TOK, 256>>>(out);
}